// round 2
// baseline (speedup 1.0000x reference)
#include <cuda_runtime.h>
#include <math.h>

#define NMAX 20000
#define EMAX 320000
#define TEMAX (EMAX + NMAX)
#define BMAXG 64
#define S2S_CAP 4096

// ---------------- static device scratch (no allocations allowed) ----------------
__device__ __align__(16) float g_h[NMAX * 256];     // GEMM output (pre-attention features)
__device__ __align__(16) float g_feat[NMAX * 256];  // layer output / next layer input
__device__ float g_s[NMAX * 4];
__device__ float g_d[NMAX * 4];
__device__ int g_rowptr[NMAX + 1];
__device__ int g_wptr[NMAX];       // doubles as counts, then write cursors
__device__ int g_col[TEMAX];
__device__ int g_gcnt[BMAXG];
__device__ int g_gptr[BMAXG + 1];
__device__ float g_qstar[BMAXG * 256];
__device__ float g_hs[BMAXG * 128];
__device__ float g_cs[BMAXG * 128];
__device__ float g_gf[BMAXG * 32];

// ---------------- init ----------------
__global__ void k_init(int n) {
    int i = blockIdx.x * blockDim.x + threadIdx.x;
    if (i < n) g_wptr[i] = 0;
    if (i < BMAXG) g_gcnt[i] = 0;
    if (i < BMAXG * 256) g_qstar[i] = 0.f;
    if (i < BMAXG * 128) { g_hs[i] = 0.f; g_cs[i] = 0.f; }
}

// ---------------- CSR build ----------------
__global__ void k_edge_hist(const int* __restrict__ ei, int E, int n) {
    int i = blockIdx.x * blockDim.x + threadIdx.x;
    int TE = E + n;
    if (i >= TE) return;
    int dv = (i < E) ? ei[E + i] : (i - E);
    atomicAdd(&g_wptr[dv], 1);
}

__global__ void k_batch_hist(const int* __restrict__ batch, int n) {
    int i = blockIdx.x * blockDim.x + threadIdx.x;
    if (i < n) atomicAdd(&g_gcnt[batch[i]], 1);
}

// single-block exclusive scan; optionally mirrors offsets into wcopy
__global__ void k_scan(const int* __restrict__ cnt, int n, int* __restrict__ outp,
                       int* __restrict__ wcopy) {
    __shared__ int part[1024];
    int tid = threadIdx.x;
    int chunk = (n + 1023) >> 10;
    int s0 = tid * chunk;
    int s1 = s0 + chunk; if (s1 > n) s1 = n;
    int s = 0;
    for (int i = s0; i < s1; i++) s += cnt[i];
    part[tid] = s;
    __syncthreads();
    for (int off = 1; off < 1024; off <<= 1) {
        int v = (tid >= off) ? part[tid - off] : 0;
        __syncthreads();
        part[tid] += v;
        __syncthreads();
    }
    int run = (tid > 0) ? part[tid - 1] : 0;
    for (int i = s0; i < s1; i++) {
        int c = cnt[i];          // read before any aliasing write
        outp[i] = run;
        if (wcopy) wcopy[i] = run;
        run += c;
    }
    if (tid == 1023) outp[n] = part[1023];
}

__global__ void k_edge_scatter(const int* __restrict__ ei, int E, int n) {
    int i = blockIdx.x * blockDim.x + threadIdx.x;
    int TE = E + n;
    if (i >= TE) return;
    int sv, dv;
    if (i < E) { sv = ei[i]; dv = ei[E + i]; } else { sv = dv = i - E; }
    int pos = atomicAdd(&g_wptr[dv], 1);
    g_col[pos] = sv;
}

// ---------------- GEMM: Out[n,M] = A[n,K] @ W[K,M], fp32, 128x64 tile ----------------
__global__ __launch_bounds__(256) void k_gemm(const float* __restrict__ A,
                                              const float* __restrict__ W,
                                              float* __restrict__ Out,
                                              int n, int K, int M) {
    __shared__ float As[16][128];
    __shared__ float Bs[16][64];
    int tid = threadIdx.x;
    int tx = tid & 15, ty = tid >> 4;
    int rb = blockIdx.x * 128;
    int cb = blockIdx.y * 64;

    float acc[8][4];
#pragma unroll
    for (int i = 0; i < 8; i++)
#pragma unroll
        for (int j = 0; j < 4; j++) acc[i][j] = 0.f;

    for (int k0 = 0; k0 < K; k0 += 16) {
#pragma unroll
        for (int t = 0; t < 2; t++) {
            int idx = tid + t * 256;          // 512 float4 loads for A tile
            int r = idx >> 2;                 // 0..127
            int kc = (idx & 3) << 2;          // 0,4,8,12
            int gr = rb + r; if (gr >= n) gr = n - 1;
            float4 v = *(const float4*)(A + (size_t)gr * K + k0 + kc);
            As[kc + 0][r] = v.x; As[kc + 1][r] = v.y;
            As[kc + 2][r] = v.z; As[kc + 3][r] = v.w;
        }
        {
            int r = tid >> 4;                 // 0..15
            int c = (tid & 15) << 2;          // 0..60
            float4 v = *(const float4*)(W + (size_t)(k0 + r) * M + cb + c);
            *(float4*)&Bs[r][c] = v;
        }
        __syncthreads();
#pragma unroll
        for (int kk = 0; kk < 16; kk++) {
            float4 a0 = *(float4*)&As[kk][ty * 8];
            float4 a1 = *(float4*)&As[kk][ty * 8 + 4];
            float4 b0 = *(float4*)&Bs[kk][tx * 4];
            float av[8] = {a0.x, a0.y, a0.z, a0.w, a1.x, a1.y, a1.z, a1.w};
            float bv[4] = {b0.x, b0.y, b0.z, b0.w};
#pragma unroll
            for (int i = 0; i < 8; i++)
#pragma unroll
                for (int j = 0; j < 4; j++) acc[i][j] = fmaf(av[i], bv[j], acc[i][j]);
        }
        __syncthreads();
    }
#pragma unroll
    for (int i = 0; i < 8; i++) {
        int gr = rb + ty * 8 + i;
        if (gr < n) {
            float4 o = make_float4(acc[i][0], acc[i][1], acc[i][2], acc[i][3]);
            *(float4*)(Out + (size_t)gr * M + cb + tx * 4) = o;
        }
    }
}

// ---------------- per-(node,head) attention logits: warp per row ----------------
template <int H, int C>
__global__ void k_sd(const float* __restrict__ h, const float* __restrict__ asrc,
                     const float* __restrict__ adst, int n) {
    int w = (blockIdx.x * blockDim.x + threadIdx.x) >> 5;
    int lane = threadIdx.x & 31;
    if (w >= n * H) return;
    int hh = w % H;
    const float* hp = h + (size_t)w * C;
    float ss = 0.f, dd = 0.f;
    for (int c = lane; c < C; c += 32) {
        float hv = hp[c];
        ss = fmaf(hv, asrc[hh * C + c], ss);
        dd = fmaf(hv, adst[hh * C + c], dd);
    }
#pragma unroll
    for (int off = 16; off > 0; off >>= 1) {
        ss += __shfl_xor_sync(0xffffffffu, ss, off);
        dd += __shfl_xor_sync(0xffffffffu, dd, off);
    }
    if (lane == 0) { g_s[w] = ss; g_d[w] = dd; }
}

// ---------------- GAT attention + scatter + bias + ELU: warp per dst node ----------------
template <int H, int C>
__global__ void k_attn(const float* __restrict__ h, const float* __restrict__ bias,
                       float* __restrict__ out, int n) {
    int v = (blockIdx.x * blockDim.x + threadIdx.x) >> 5;
    int lane = threadIdx.x & 31;
    if (v >= n) return;
    int beg = g_rowptr[v], end = g_rowptr[v + 1];

    float dv[H];
#pragma unroll
    for (int t = 0; t < H; t++) dv[t] = g_d[v * H + t];

    // pass 1: per-head max over incoming edges
    float m[H];
#pragma unroll
    for (int t = 0; t < H; t++) m[t] = -1e30f;
    for (int j = beg + lane; j < end; j += 32) {
        int u = g_col[j];
#pragma unroll
        for (int t = 0; t < H; t++) {
            float e = g_s[u * H + t] + dv[t];
            e = (e > 0.f) ? e : 0.2f * e;
            m[t] = fmaxf(m[t], e);
        }
    }
#pragma unroll
    for (int t = 0; t < H; t++)
#pragma unroll
        for (int off = 16; off > 0; off >>= 1)
            m[t] = fmaxf(m[t], __shfl_xor_sync(0xffffffffu, m[t], off));

    // pass 2: serial edges, channel-parallel lanes
    constexpr int F = H * C / 32;   // 8 (layers 1/2), 4 (layer 3)
    int hh = (lane * F) / C;
    float mh = m[hh];
    float dvh = dv[hh];
    float acc[F];
#pragma unroll
    for (int q = 0; q < F; q++) acc[q] = 0.f;
    float den = 0.f;

    for (int j = beg; j < end; j++) {
        int u = g_col[j];
        float e = g_s[u * H + hh] + dvh;
        e = (e > 0.f) ? e : 0.2f * e;
        float ex = __expf(e - mh);
        den += ex;
        const float4* hp = (const float4*)(h + (size_t)u * (H * C)) + lane * (F / 4);
#pragma unroll
        for (int q = 0; q < F / 4; q++) {
            float4 hv = hp[q];
            acc[q * 4 + 0] = fmaf(ex, hv.x, acc[q * 4 + 0]);
            acc[q * 4 + 1] = fmaf(ex, hv.y, acc[q * 4 + 1]);
            acc[q * 4 + 2] = fmaf(ex, hv.z, acc[q * 4 + 2]);
            acc[q * 4 + 3] = fmaf(ex, hv.w, acc[q * 4 + 3]);
        }
    }
    float inv = 1.f / (den + 1e-16f);
#pragma unroll
    for (int q = 0; q < F; q++) {
        int c = lane * F + q;
        float o = acc[q] * inv + bias[c];
        o = (o > 0.f) ? o : expm1f(o);
        out[(size_t)v * (H * C) + c] = o;
    }
}

// ---------------- Set2Set LSTM step: one block per graph ----------------
__global__ void k_lstm(const float* __restrict__ Wih, const float* __restrict__ Whh,
                       const float* __restrict__ bih, const float* __restrict__ bhh) {
    int b = blockIdx.x;
    int j = threadIdx.x;  // 128
    __shared__ float q[256], hp[128];
    q[j] = g_qstar[b * 256 + j];
    q[j + 128] = g_qstar[b * 256 + 128 + j];
    hp[j] = g_hs[b * 128 + j];
    __syncthreads();
    float g4[4];
#pragma unroll
    for (int gi = 0; gi < 4; gi++) {
        int row = gi * 128 + j;
        float a = bih[row] + bhh[row];
        const float* wi = Wih + (size_t)row * 256;
        const float* wh = Whh + (size_t)row * 128;
        for (int k = 0; k < 256; k++) a = fmaf(q[k], wi[k], a);
        for (int k = 0; k < 128; k++) a = fmaf(hp[k], wh[k], a);
        g4[gi] = a;
    }
    float ig = 1.f / (1.f + __expf(-g4[0]));
    float fg = 1.f / (1.f + __expf(-g4[1]));
    float gg = tanhf(g4[2]);
    float og = 1.f / (1.f + __expf(-g4[3]));
    float c = fg * g_cs[b * 128 + j] + ig * gg;
    float hh = og * tanhf(c);
    g_cs[b * 128 + j] = c;
    g_hs[b * 128 + j] = hh;
}

// ---------------- Set2Set attention pool: one block per graph ----------------
__global__ void k_pool(const float* __restrict__ x) {
    int g = blockIdx.x;
    int tid = threadIdx.x;  // 128
    __shared__ float q[128];
    __shared__ float e_sh[S2S_CAP];
    __shared__ float red[128];
    __shared__ float sval;
    int beg = g_gptr[g], end = g_gptr[g + 1];
    int cnt = end - beg;
    q[tid] = g_hs[g * 128 + tid];
    __syncthreads();

    float lmax = -1e30f;
    for (int i = tid; i < cnt; i += 128) {
        const float* xp = x + (size_t)(beg + i) * 128;
        float e = 0.f;
        for (int k = 0; k < 128; k++) e = fmaf(xp[k], q[k], e);
        if (i < S2S_CAP) e_sh[i] = e;
        lmax = fmaxf(lmax, e);
    }
    red[tid] = lmax;
    __syncthreads();
    for (int s = 64; s > 0; s >>= 1) {
        if (tid < s) red[tid] = fmaxf(red[tid], red[tid + s]);
        __syncthreads();
    }
    if (tid == 0) sval = red[0];
    __syncthreads();
    float emax = sval;
    __syncthreads();

    float lsum = 0.f;
    for (int i = tid; i < cnt; i += 128) {
        float e;
        if (i < S2S_CAP) e = e_sh[i];
        else {
            const float* xp = x + (size_t)(beg + i) * 128;
            e = 0.f;
            for (int k = 0; k < 128; k++) e = fmaf(xp[k], q[k], e);
        }
        float a = __expf(e - emax);
        if (i < S2S_CAP) e_sh[i] = a;
        lsum += a;
    }
    red[tid] = lsum;
    __syncthreads();
    for (int s = 64; s > 0; s >>= 1) {
        if (tid < s) red[tid] += red[tid + s];
        __syncthreads();
    }
    if (tid == 0) sval = red[0];
    __syncthreads();
    float inv = 1.f / (sval + 1e-16f);

    // r: thread = channel
    float r = 0.f;
    for (int i = 0; i < cnt; i++) {
        float a;
        if (i < S2S_CAP) a = e_sh[i];
        else {
            const float* xp = x + (size_t)(beg + i) * 128;
            float e = 0.f;
            for (int k = 0; k < 128; k++) e = fmaf(xp[k], q[k], e);
            a = __expf(e - emax);
        }
        r = fmaf(a, x[(size_t)(beg + i) * 128 + tid], r);
    }
    g_qstar[g * 256 + tid] = q[tid];
    g_qstar[g * 256 + 128 + tid] = r * inv;
}

// ---------------- graph-feature MLP ----------------
__global__ void k_gf(const float* __restrict__ gfeat, const float* __restrict__ gW1,
                     const float* __restrict__ gb1, const float* __restrict__ gW2,
                     const float* __restrict__ gb2) {
    int b = blockIdx.x;
    int j = threadIdx.x;  // 64
    __shared__ float hid[64];
    float a = gb1[j];
    for (int k = 0; k < 9; k++) a = fmaf(gfeat[b * 9 + k], gW1[k * 64 + j], a);
    hid[j] = fmaxf(a, 0.f);
    __syncthreads();
    if (j < 32) {
        float o = gb2[j];
        for (int k = 0; k < 64; k++) o = fmaf(hid[k], gW2[k * 32 + j], o);
        g_gf[b * 32 + j] = o;
    }
}

// ---------------- final scorer MLP ----------------
__global__ void k_final(const float* __restrict__ mW1, const float* __restrict__ mb1,
                        const float* __restrict__ mW2, const float* __restrict__ mb2,
                        float* __restrict__ out) {
    int b = blockIdx.x;
    int j = threadIdx.x;  // 128
    __shared__ float z[288];
    __shared__ float hid[128];
    z[j] = g_qstar[b * 256 + j];
    z[j + 128] = g_qstar[b * 256 + 128 + j];
    if (j < 32) z[256 + j] = g_gf[b * 32 + j];
    __syncthreads();
    float a = mb1[j];
    for (int k = 0; k < 288; k++) a = fmaf(z[k], mW1[k * 128 + j], a);
    hid[j] = fmaxf(a, 0.f);
    __syncthreads();
    if (j < 4) {
        float o = mb2[j];
        for (int k = 0; k < 128; k++) o = fmaf(hid[k], mW2[k * 4 + j], o);
        out[b * 4 + j] = o;
    }
}

// ---------------- launch ----------------
extern "C" void kernel_launch(void* const* d_in, const int* in_sizes, int n_in,
                              void* d_out, int out_size) {
    const float* x      = (const float*)d_in[0];
    const int*   ei     = (const int*)d_in[1];
    const int*   batch  = (const int*)d_in[2];
    const float* gfeat  = (const float*)d_in[3];
    const float* W1     = (const float*)d_in[4];
    const float* a_src1 = (const float*)d_in[5];
    const float* a_dst1 = (const float*)d_in[6];
    const float* b1     = (const float*)d_in[7];
    const float* W2     = (const float*)d_in[8];
    const float* a_src2 = (const float*)d_in[9];
    const float* a_dst2 = (const float*)d_in[10];
    const float* b2     = (const float*)d_in[11];
    const float* W3     = (const float*)d_in[12];
    const float* a_src3 = (const float*)d_in[13];
    const float* a_dst3 = (const float*)d_in[14];
    const float* b3     = (const float*)d_in[15];
    const float* Wih    = (const float*)d_in[16];
    const float* Whh    = (const float*)d_in[17];
    const float* bih    = (const float*)d_in[18];
    const float* bhh    = (const float*)d_in[19];
    const float* gW1    = (const float*)d_in[20];
    const float* gb1    = (const float*)d_in[21];
    const float* gW2    = (const float*)d_in[22];
    const float* gb2    = (const float*)d_in[23];
    const float* mW1    = (const float*)d_in[24];
    const float* mb1    = (const float*)d_in[25];
    const float* mW2    = (const float*)d_in[26];
    const float* mb2    = (const float*)d_in[27];

    int n  = in_sizes[0] / 128;
    int E  = in_sizes[1] / 2;
    int nb = in_sizes[3] / 9;
    int TE = E + n;

    float *ph, *pfeat;
    int *p_wptr, *p_rowptr, *p_gcnt, *p_gptr;
    cudaGetSymbolAddress((void**)&ph, g_h);
    cudaGetSymbolAddress((void**)&pfeat, g_feat);
    cudaGetSymbolAddress((void**)&p_wptr, g_wptr);
    cudaGetSymbolAddress((void**)&p_rowptr, g_rowptr);
    cudaGetSymbolAddress((void**)&p_gcnt, g_gcnt);
    cudaGetSymbolAddress((void**)&p_gptr, g_gptr);

    // init + CSR build (graph topology is the same across all layers)
    k_init<<<(n + 255) / 256, 256>>>(n);
    k_edge_hist<<<(TE + 255) / 256, 256>>>(ei, E, n);
    k_batch_hist<<<(n + 255) / 256, 256>>>(batch, n);
    k_scan<<<1, 1024>>>(p_wptr, n, p_rowptr, p_wptr);
    k_scan<<<1, 1024>>>(p_gcnt, nb, p_gptr, (int*)nullptr);
    k_edge_scatter<<<(TE + 255) / 256, 256>>>(ei, E, n);

    dim3 gg256((n + 127) / 128, 4);  // M=256
    dim3 gg128((n + 127) / 128, 2);  // M=128
    int sd_blocks4 = (n * 4 * 32 + 255) / 256;
    int sd_blocks1 = (n * 1 * 32 + 255) / 256;
    int attn_blocks = (n * 32 + 255) / 256;

    // layer 1: 128 -> 4x64
    k_gemm<<<gg256, 256>>>(x, W1, ph, n, 128, 256);
    k_sd<4, 64><<<sd_blocks4, 256>>>(ph, a_src1, a_dst1, n);
    k_attn<4, 64><<<attn_blocks, 256>>>(ph, b1, pfeat, n);

    // layer 2: 256 -> 4x64
    k_gemm<<<gg256, 256>>>(pfeat, W2, ph, n, 256, 256);
    k_sd<4, 64><<<sd_blocks4, 256>>>(ph, a_src2, a_dst2, n);
    k_attn<4, 64><<<attn_blocks, 256>>>(ph, b2, pfeat, n);

    // layer 3: 256 -> 1x128
    k_gemm<<<gg128, 256>>>(pfeat, W3, ph, n, 256, 128);
    k_sd<1, 128><<<sd_blocks1, 256>>>(ph, a_src3, a_dst3, n);
    k_attn<1, 128><<<attn_blocks, 256>>>(ph, b3, pfeat, n);

    // Set2Set (3 steps)
    for (int step = 0; step < 3; step++) {
        k_lstm<<<nb, 128>>>(Wih, Whh, bih, bhh);
        k_pool<<<nb, 128>>>(pfeat);
    }

    // heads
    k_gf<<<nb, 64>>>(gfeat, gW1, gb1, gW2, gb2);
    k_final<<<nb, 128>>>(mW1, mb1, mW2, mb2, (float*)d_out);
}

// round 4
// speedup vs baseline: 1.7067x; 1.7067x over previous
#include <cuda_runtime.h>
#include <math.h>
#include <stdint.h>

#define NMAX 20000
#define EMAX 320000
#define TEMAX (EMAX + NMAX)
#define BMAXG 64
#define S2S_CAP 4096

__device__ __align__(16) float g_h[NMAX * 256];
__device__ __align__(16) float g_feat[NMAX * 256];
__device__ float g_s[NMAX * 4];
__device__ float g_d[NMAX * 4];
__device__ int g_rowptr[NMAX + 1];
__device__ int g_wptr[NMAX];
__device__ int g_col[TEMAX];
__device__ int g_gcnt[BMAXG];
__device__ int g_gptr[BMAXG + 1];
__device__ int g_tmp[NMAX];
__device__ int g_blksum[32];
__device__ float g_qstar[BMAXG * 256];
__device__ float g_hs[BMAXG * 128];
__device__ float g_cs[BMAXG * 128];
__device__ float g_gf[BMAXG * 32];

__device__ __forceinline__ float f2tf(float a) {
    uint32_t r;
    asm("cvt.rn.tf32.f32 %0, %1;" : "=r"(r) : "f"(a));
    return __uint_as_float(r);
}
__device__ __forceinline__ void mma8(float* c, const uint32_t* a, const uint32_t* b) {
    asm volatile(
        "mma.sync.aligned.m16n8k8.row.col.f32.tf32.tf32.f32 "
        "{%0,%1,%2,%3}, {%4,%5,%6,%7}, {%8,%9}, {%0,%1,%2,%3};"
        : "+f"(c[0]), "+f"(c[1]), "+f"(c[2]), "+f"(c[3])
        : "r"(a[0]), "r"(a[1]), "r"(a[2]), "r"(a[3]), "r"(b[0]), "r"(b[1]));
}

// ---- init + CSR ----
__global__ void k_init(int n) {
    int i = blockIdx.x * blockDim.x + threadIdx.x;
    if (i < n) g_wptr[i] = 0;
    if (i < BMAXG) g_gcnt[i] = 0;
    if (i < BMAXG * 256) g_qstar[i] = 0.f;
    if (i < BMAXG * 128) { g_hs[i] = 0.f; g_cs[i] = 0.f; }
}
__global__ void k_edge_hist(const int* __restrict__ ei, int E, int n) {
    int i = blockIdx.x * blockDim.x + threadIdx.x;
    if (i >= E + n) return;
    int dv = (i < E) ? ei[E + i] : (i - E);
    atomicAdd(&g_wptr[dv], 1);
}
__global__ void k_batch_hist(const int* __restrict__ batch, int n) {
    int i = blockIdx.x * blockDim.x + threadIdx.x;
    if (i < n) atomicAdd(&g_gcnt[batch[i]], 1);
}
__global__ __launch_bounds__(1024) void k_scan_part(int n) {
    __shared__ int wsum[32];
    int tid = threadIdx.x, lane = tid & 31, wid = tid >> 5;
    int i = blockIdx.x * 1024 + tid;
    int v = (i < n) ? g_wptr[i] : 0;
    int x = v;
#pragma unroll
    for (int o = 1; o < 32; o <<= 1) { int y = __shfl_up_sync(~0u, x, o); if (lane >= o) x += y; }
    if (lane == 31) wsum[wid] = x;
    __syncthreads();
    if (wid == 0) {
        int w = wsum[lane];
#pragma unroll
        for (int o = 1; o < 32; o <<= 1) { int y = __shfl_up_sync(~0u, w, o); if (lane >= o) w += y; }
        wsum[lane] = w;
    }
    __syncthreads();
    int excl = x - v + ((wid > 0) ? wsum[wid - 1] : 0);
    if (i < n) g_tmp[i] = excl;
    if (tid == 1023) g_blksum[blockIdx.x] = wsum[31];
}
__global__ void k_scan_top(int nb) {
    int lane = threadIdx.x;
    int v = (lane < nb) ? g_blksum[lane] : 0;
    int x = v;
#pragma unroll
    for (int o = 1; o < 32; o <<= 1) { int y = __shfl_up_sync(~0u, x, o); if (lane >= o) x += y; }
    if (lane < nb) g_blksum[lane] = x - v;
}
__global__ __launch_bounds__(1024) void k_scan_apply(int n, int total) {
    int i = blockIdx.x * 1024 + threadIdx.x;
    if (i < n) { int r = g_tmp[i] + g_blksum[blockIdx.x]; g_rowptr[i] = r; g_wptr[i] = r; }
    if (i == 0) g_rowptr[n] = total;
}
__global__ void k_gscan(int nb) {
    __shared__ int s[64];
    int tid = threadIdx.x;
    s[tid] = (tid < nb) ? g_gcnt[tid] : 0;
    __syncthreads();
    for (int o = 1; o < 64; o <<= 1) {
        int v = (tid >= o) ? s[tid - o] : 0;
        __syncthreads(); s[tid] += v; __syncthreads();
    }
    g_gptr[tid + 1] = s[tid];
    if (tid == 0) g_gptr[0] = 0;
}
__global__ void k_edge_scatter(const int* __restrict__ ei, int E, int n) {
    int i = blockIdx.x * blockDim.x + threadIdx.x;
    if (i >= E + n) return;
    int sv, dv;
    if (i < E) { sv = ei[i]; dv = ei[E + i]; } else { sv = dv = i - E; }
    g_col[atomicAdd(&g_wptr[dv], 1)] = sv;
}

// ---- tensor-core tf32 GEMM (hi/lo split): Out[n,M] = A[n,K] @ W[K,M] ----
// CTA 128x64, 8 warps (4m x 2n), warp tile 32x32, mma m16n8k8.
__global__ __launch_bounds__(256) void k_gemm_mma(const float* __restrict__ A,
                                                 const float* __restrict__ W,
                                                 float* __restrict__ Out,
                                                 int n, int K, int M) {
    __shared__ float As[128][36];  // [m][k], pad 36 -> conflict-free frag reads
    __shared__ float Bs[32][72];   // [k][n], pad 72 -> conflict-free frag reads
    int tid = threadIdx.x, lane = tid & 31, wid = tid >> 5;
    int warp_m = wid & 3, warp_n = wid >> 2;
    int rb = blockIdx.x * 128, cb = blockIdx.y * 64;
    int m0 = warp_m * 32, n0 = warp_n * 32;
    int row = lane >> 2, col = lane & 3;

    float acc[2][4][4];
#pragma unroll
    for (int a = 0; a < 2; a++)
#pragma unroll
        for (int b = 0; b < 4; b++)
#pragma unroll
            for (int q = 0; q < 4; q++) acc[a][b][q] = 0.f;

    for (int k0 = 0; k0 < K; k0 += 32) {
#pragma unroll
        for (int i = 0; i < 4; i++) {   // A tile 128x32
            int idx = tid + i * 256;
            int r = idx >> 3, c4 = (idx & 7) << 2;
            int gr = rb + r; if (gr >= n) gr = n - 1;
            *(float4*)&As[r][c4] = *(const float4*)(A + (size_t)gr * K + k0 + c4);
        }
#pragma unroll
        for (int i = 0; i < 2; i++) {   // B tile 32x64
            int idx = tid + i * 256;
            int kk = idx >> 4, c4 = (idx & 15) << 2;
            *(float4*)&Bs[kk][c4] = *(const float4*)(W + (size_t)(k0 + kk) * M + cb + c4);
        }
        __syncthreads();
#pragma unroll
        for (int kk = 0; kk < 32; kk += 8) {
            uint32_t ahi[2][4], alo[2][4], bhi[4][2], blo[4][2];
#pragma unroll
            for (int mt = 0; mt < 2; mt++)
#pragma unroll
                for (int q = 0; q < 4; q++) {
                    float v = As[m0 + mt * 16 + row + (q & 1) * 8][kk + col + (q >> 1) * 4];
                    float h = f2tf(v);
                    ahi[mt][q] = __float_as_uint(h);
                    alo[mt][q] = __float_as_uint(f2tf(v - h));
                }
#pragma unroll
            for (int nt = 0; nt < 4; nt++)
#pragma unroll
                for (int q = 0; q < 2; q++) {
                    float v = Bs[kk + col + q * 4][n0 + nt * 8 + row];
                    float h = f2tf(v);
                    bhi[nt][q] = __float_as_uint(h);
                    blo[nt][q] = __float_as_uint(f2tf(v - h));
                }
#pragma unroll
            for (int mt = 0; mt < 2; mt++)
#pragma unroll
                for (int nt = 0; nt < 4; nt++) {
                    mma8(acc[mt][nt], ahi[mt], bhi[nt]);
                    mma8(acc[mt][nt], ahi[mt], blo[nt]);
                    mma8(acc[mt][nt], alo[mt], bhi[nt]);
                }
        }
        __syncthreads();
    }
#pragma unroll
    for (int mt = 0; mt < 2; mt++)
#pragma unroll
        for (int q = 0; q < 2; q++) {
            int gr = rb + m0 + mt * 16 + row + q * 8;
            if (gr < n) {
#pragma unroll
                for (int nt = 0; nt < 4; nt++) {
                    int gc = cb + n0 + nt * 8 + col * 2;
                    *(float2*)(Out + (size_t)gr * M + gc) =
                        make_float2(acc[mt][nt][q * 2], acc[mt][nt][q * 2 + 1]);
                }
            }
        }
}

// ---- per-(node,head) logits: warp per row ----
template <int H, int C>
__global__ void k_sd(const float* __restrict__ h, const float* __restrict__ asrc,
                     const float* __restrict__ adst, int n) {
    int w = (blockIdx.x * blockDim.x + threadIdx.x) >> 5;
    int lane = threadIdx.x & 31;
    if (w >= n * H) return;
    int hh = w % H;
    const float* hp = h + (size_t)w * C;
    float ss = 0.f, dd = 0.f;
    for (int c = lane; c < C; c += 32) {
        float hv = hp[c];
        ss = fmaf(hv, asrc[hh * C + c], ss);
        dd = fmaf(hv, adst[hh * C + c], dd);
    }
#pragma unroll
    for (int off = 16; off > 0; off >>= 1) {
        ss += __shfl_xor_sync(~0u, ss, off);
        dd += __shfl_xor_sync(~0u, dd, off);
    }
    if (lane == 0) { g_s[w] = ss; g_d[w] = dd; }
}

// ---- GAT attention + scatter + bias + ELU: warp per dst node ----
template <int H, int C>
__global__ void k_attn(const float* __restrict__ h, const float* __restrict__ bias,
                       float* __restrict__ out, int n) {
    int v = (blockIdx.x * blockDim.x + threadIdx.x) >> 5;
    int lane = threadIdx.x & 31;
    if (v >= n) return;
    int beg = g_rowptr[v], end = g_rowptr[v + 1];
    float dv[H], m[H];
#pragma unroll
    for (int t = 0; t < H; t++) { dv[t] = g_d[v * H + t]; m[t] = -1e30f; }
    for (int j = beg + lane; j < end; j += 32) {
        int u = g_col[j];
#pragma unroll
        for (int t = 0; t < H; t++) {
            float e = g_s[u * H + t] + dv[t];
            e = (e > 0.f) ? e : 0.2f * e;
            m[t] = fmaxf(m[t], e);
        }
    }
#pragma unroll
    for (int t = 0; t < H; t++)
#pragma unroll
        for (int off = 16; off > 0; off >>= 1)
            m[t] = fmaxf(m[t], __shfl_xor_sync(~0u, m[t], off));

    constexpr int F = H * C / 32;
    int hh = (lane * F) / C;
    float mh = m[hh], dvh = dv[hh];
    float acc[F];
#pragma unroll
    for (int q = 0; q < F; q++) acc[q] = 0.f;
    float den = 0.f;
    for (int j = beg; j < end; j++) {
        int u = g_col[j];
        float e = g_s[u * H + hh] + dvh;
        e = (e > 0.f) ? e : 0.2f * e;
        float ex = __expf(e - mh);
        den += ex;
        const float4* hp = (const float4*)(h + (size_t)u * (H * C)) + lane * (F / 4);
#pragma unroll
        for (int q = 0; q < F / 4; q++) {
            float4 hv = hp[q];
            acc[q * 4 + 0] = fmaf(ex, hv.x, acc[q * 4 + 0]);
            acc[q * 4 + 1] = fmaf(ex, hv.y, acc[q * 4 + 1]);
            acc[q * 4 + 2] = fmaf(ex, hv.z, acc[q * 4 + 2]);
            acc[q * 4 + 3] = fmaf(ex, hv.w, acc[q * 4 + 3]);
        }
    }
    float inv = 1.f / (den + 1e-16f);
#pragma unroll
    for (int q = 0; q < F; q++) {
        int c = lane * F + q;
        float o = acc[q] * inv + bias[c];
        o = (o > 0.f) ? o : expm1f(o);
        out[(size_t)v * (H * C) + c] = o;
    }
}

// ---- Set2Set LSTM ----
__global__ void k_lstm(const float* __restrict__ Wih, const float* __restrict__ Whh,
                       const float* __restrict__ bih, const float* __restrict__ bhh) {
    int b = blockIdx.x, j = threadIdx.x;
    __shared__ float q[256], hp[128];
    q[j] = g_qstar[b * 256 + j];
    q[j + 128] = g_qstar[b * 256 + 128 + j];
    hp[j] = g_hs[b * 128 + j];
    __syncthreads();
    float g4[4];
#pragma unroll
    for (int gi = 0; gi < 4; gi++) {
        int rowi = gi * 128 + j;
        float a = bih[rowi] + bhh[rowi];
        const float* wi = Wih + (size_t)rowi * 256;
        const float* wh = Whh + (size_t)rowi * 128;
        for (int k = 0; k < 256; k++) a = fmaf(q[k], wi[k], a);
        for (int k = 0; k < 128; k++) a = fmaf(hp[k], wh[k], a);
        g4[gi] = a;
    }
    float ig = 1.f / (1.f + __expf(-g4[0]));
    float fg = 1.f / (1.f + __expf(-g4[1]));
    float gg = tanhf(g4[2]);
    float og = 1.f / (1.f + __expf(-g4[3]));
    float c = fg * g_cs[b * 128 + j] + ig * gg;
    g_cs[b * 128 + j] = c;
    g_hs[b * 128 + j] = og * tanhf(c);
}

// ---- Set2Set pool ----
__global__ void k_pool(const float* __restrict__ x) {
    int g = blockIdx.x, tid = threadIdx.x;
    __shared__ float q[128], e_sh[S2S_CAP], red[128], sval;
    int beg = g_gptr[g], cnt = g_gptr[g + 1] - beg;
    q[tid] = g_hs[g * 128 + tid];
    __syncthreads();
    float lmax = -1e30f;
    for (int i = tid; i < cnt; i += 128) {
        const float* xp = x + (size_t)(beg + i) * 128;
        float e = 0.f;
        for (int k = 0; k < 128; k++) e = fmaf(xp[k], q[k], e);
        if (i < S2S_CAP) e_sh[i] = e;
        lmax = fmaxf(lmax, e);
    }
    red[tid] = lmax;
    __syncthreads();
    for (int s = 64; s > 0; s >>= 1) { if (tid < s) red[tid] = fmaxf(red[tid], red[tid + s]); __syncthreads(); }
    if (tid == 0) sval = red[0];
    __syncthreads();
    float emax = sval;
    __syncthreads();
    float lsum = 0.f;
    for (int i = tid; i < cnt; i += 128) {
        float e;
        if (i < S2S_CAP) e = e_sh[i];
        else {
            const float* xp = x + (size_t)(beg + i) * 128;
            e = 0.f;
            for (int k = 0; k < 128; k++) e = fmaf(xp[k], q[k], e);
        }
        float a = __expf(e - emax);
        if (i < S2S_CAP) e_sh[i] = a;
        lsum += a;
    }
    red[tid] = lsum;
    __syncthreads();
    for (int s = 64; s > 0; s >>= 1) { if (tid < s) red[tid] += red[tid + s]; __syncthreads(); }
    if (tid == 0) sval = red[0];
    __syncthreads();
    float inv = 1.f / (sval + 1e-16f);
    float r = 0.f;
    for (int i = 0; i < cnt; i++) {
        float a;
        if (i < S2S_CAP) a = e_sh[i];
        else {
            const float* xp = x + (size_t)(beg + i) * 128;
            float e = 0.f;
            for (int k = 0; k < 128; k++) e = fmaf(xp[k], q[k], e);
            a = __expf(e - emax);
        }
        r = fmaf(a, x[(size_t)(beg + i) * 128 + tid], r);
    }
    g_qstar[g * 256 + tid] = q[tid];
    g_qstar[g * 256 + 128 + tid] = r * inv;
}

__global__ void k_gf(const float* __restrict__ gfeat, const float* __restrict__ gW1,
                     const float* __restrict__ gb1, const float* __restrict__ gW2,
                     const float* __restrict__ gb2) {
    int b = blockIdx.x, j = threadIdx.x;
    __shared__ float hid[64];
    float a = gb1[j];
    for (int k = 0; k < 9; k++) a = fmaf(gfeat[b * 9 + k], gW1[k * 64 + j], a);
    hid[j] = fmaxf(a, 0.f);
    __syncthreads();
    if (j < 32) {
        float o = gb2[j];
        for (int k = 0; k < 64; k++) o = fmaf(hid[k], gW2[k * 32 + j], o);
        g_gf[b * 32 + j] = o;
    }
}

__global__ void k_final(const float* __restrict__ mW1, const float* __restrict__ mb1,
                        const float* __restrict__ mW2, const float* __restrict__ mb2,
                        float* __restrict__ out) {
    int b = blockIdx.x, j = threadIdx.x;
    __shared__ float z[288], hid[128];
    z[j] = g_qstar[b * 256 + j];
    z[j + 128] = g_qstar[b * 256 + 128 + j];
    if (j < 32) z[256 + j] = g_gf[b * 32 + j];
    __syncthreads();
    float a = mb1[j];
    for (int k = 0; k < 288; k++) a = fmaf(z[k], mW1[k * 128 + j], a);
    hid[j] = fmaxf(a, 0.f);
    __syncthreads();
    if (j < 4) {
        float o = mb2[j];
        for (int k = 0; k < 128; k++) o = fmaf(hid[k], mW2[k * 4 + j], o);
        out[b * 4 + j] = o;
    }
}

// ---- launch ----
extern "C" void kernel_launch(void* const* d_in, const int* in_sizes, int n_in,
                              void* d_out, int out_size) {
    const float* x      = (const float*)d_in[0];
    const int*   ei     = (const int*)d_in[1];
    const int*   batch  = (const int*)d_in[2];
    const float* gfeat  = (const float*)d_in[3];
    const float* W1     = (const float*)d_in[4];
    const float* a_src1 = (const float*)d_in[5];
    const float* a_dst1 = (const float*)d_in[6];
    const float* b1     = (const float*)d_in[7];
    const float* W2     = (const float*)d_in[8];
    const float* a_src2 = (const float*)d_in[9];
    const float* a_dst2 = (const float*)d_in[10];
    const float* b2     = (const float*)d_in[11];
    const float* W3     = (const float*)d_in[12];
    const float* a_src3 = (const float*)d_in[13];
    const float* a_dst3 = (const float*)d_in[14];
    const float* b3     = (const float*)d_in[15];
    const float* Wih    = (const float*)d_in[16];
    const float* Whh    = (const float*)d_in[17];
    const float* bih    = (const float*)d_in[18];
    const float* bhh    = (const float*)d_in[19];
    const float* gW1    = (const float*)d_in[20];
    const float* gb1    = (const float*)d_in[21];
    const float* gW2    = (const float*)d_in[22];
    const float* gb2    = (const float*)d_in[23];
    const float* mW1    = (const float*)d_in[24];
    const float* mb1    = (const float*)d_in[25];
    const float* mW2    = (const float*)d_in[26];
    const float* mb2    = (const float*)d_in[27];

    int n  = in_sizes[0] / 128;
    int E  = in_sizes[1] / 2;
    int nb = in_sizes[3] / 9;
    int TE = E + n;

    float *ph, *pfeat;
    cudaGetSymbolAddress((void**)&ph, g_h);
    cudaGetSymbolAddress((void**)&pfeat, g_feat);

    k_init<<<(n + 255) / 256, 256>>>(n);
    k_edge_hist<<<(TE + 255) / 256, 256>>>(ei, E, n);
    k_batch_hist<<<(n + 255) / 256, 256>>>(batch, n);
    k_scan_part<<<(n + 1023) / 1024, 1024>>>(n);
    k_scan_top<<<1, 32>>>((n + 1023) / 1024);
    k_scan_apply<<<(n + 1023) / 1024, 1024>>>(n, TE);
    k_gscan<<<1, 64>>>(nb);
    k_edge_scatter<<<(TE + 255) / 256, 256>>>(ei, E, n);

    int gx = (n + 127) / 128;
    int sd_blocks4 = (n * 4 * 32 + 255) / 256;
    int sd_blocks1 = (n * 1 * 32 + 255) / 256;
    int attn_blocks = (n * 32 + 255) / 256;

    k_gemm_mma<<<dim3(gx, 4), 256>>>(x, W1, ph, n, 128, 256);
    k_sd<4, 64><<<sd_blocks4, 256>>>(ph, a_src1, a_dst1, n);
    k_attn<4, 64><<<attn_blocks, 256>>>(ph, b1, pfeat, n);

    k_gemm_mma<<<dim3(gx, 4), 256>>>(pfeat, W2, ph, n, 256, 256);
    k_sd<4, 64><<<sd_blocks4, 256>>>(ph, a_src2, a_dst2, n);
    k_attn<4, 64><<<attn_blocks, 256>>>(ph, b2, pfeat, n);

    k_gemm_mma<<<dim3(gx, 2), 256>>>(pfeat, W3, ph, n, 256, 128);
    k_sd<1, 128><<<sd_blocks1, 256>>>(ph, a_src3, a_dst3, n);
    k_attn<1, 128><<<attn_blocks, 256>>>(ph, b3, pfeat, n);

    for (int step = 0; step < 3; step++) {
        k_lstm<<<nb, 128>>>(Wih, Whh, bih, bhh);
        k_pool<<<nb, 128>>>(pfeat);
    }
    k_gf<<<nb, 64>>>(gfeat, gW1, gb1, gW2, gb2);
    k_final<<<nb, 128>>>(mW1, mb1, mW2, mb2, (float*)d_out);
}

// round 6
// speedup vs baseline: 2.4352x; 1.4268x over previous
#include <cuda_runtime.h>
#include <math.h>
#include <stdint.h>

#define NMAX 20000
#define EMAX 320000
#define TEMAX (EMAX + NMAX)
#define BMAXG 64

__device__ __align__(16) float g_h[NMAX * 256];
__device__ __align__(16) float g_feat[NMAX * 256];
__device__ float g_s[NMAX * 4];
__device__ float g_d[NMAX * 4];
__device__ int g_rowptr[NMAX + 1];
__device__ int g_wptr[NMAX];
__device__ int g_col[TEMAX];
__device__ int g_gcnt[BMAXG];
__device__ int g_gptr[BMAXG + 1];
__device__ int g_tmp[NMAX];
__device__ int g_blksum[32];

__device__ __forceinline__ float f2tf(float a) {
    uint32_t r;
    asm("cvt.rn.tf32.f32 %0, %1;" : "=r"(r) : "f"(a));
    return __uint_as_float(r);
}
__device__ __forceinline__ void mma8(float* c, const uint32_t* a, const uint32_t* b) {
    asm volatile(
        "mma.sync.aligned.m16n8k8.row.col.f32.tf32.tf32.f32 "
        "{%0,%1,%2,%3}, {%4,%5,%6,%7}, {%8,%9}, {%0,%1,%2,%3};"
        : "+f"(c[0]), "+f"(c[1]), "+f"(c[2]), "+f"(c[3])
        : "r"(a[0]), "r"(a[1]), "r"(a[2]), "r"(a[3]), "r"(b[0]), "r"(b[1]));
}

// ---- init + CSR ----
__global__ void k_init(int n) {
    int i = blockIdx.x * blockDim.x + threadIdx.x;
    if (i < n) g_wptr[i] = 0;
    if (i < BMAXG) g_gcnt[i] = 0;
}
__global__ void k_hist(const int* __restrict__ ei, const int* __restrict__ batch, int E, int n) {
    int i = blockIdx.x * blockDim.x + threadIdx.x;
    if (i < E + n) {
        int dv = (i < E) ? ei[E + i] : (i - E);
        atomicAdd(&g_wptr[dv], 1);
    }
    if (i < n) atomicAdd(&g_gcnt[batch[i]], 1);
}
__global__ __launch_bounds__(1024) void k_scan_part(int n) {
    __shared__ int wsum[32];
    int tid = threadIdx.x, lane = tid & 31, wid = tid >> 5;
    int i = blockIdx.x * 1024 + tid;
    int v = (i < n) ? g_wptr[i] : 0;
    int x = v;
#pragma unroll
    for (int o = 1; o < 32; o <<= 1) { int y = __shfl_up_sync(~0u, x, o); if (lane >= o) x += y; }
    if (lane == 31) wsum[wid] = x;
    __syncthreads();
    if (wid == 0) {
        int w = wsum[lane];
#pragma unroll
        for (int o = 1; o < 32; o <<= 1) { int y = __shfl_up_sync(~0u, w, o); if (lane >= o) w += y; }
        wsum[lane] = w;
    }
    __syncthreads();
    int excl = x - v + ((wid > 0) ? wsum[wid - 1] : 0);
    if (i < n) g_tmp[i] = excl;
    if (tid == 1023) g_blksum[blockIdx.x] = wsum[31];
}
__global__ __launch_bounds__(1024) void k_scan_apply(int n, int total) {
    __shared__ int bs[32];
    int tid = threadIdx.x;
    if (tid < 32) {
        int nblk = gridDim.x;
        int v = (tid < nblk) ? g_blksum[tid] : 0;
        int x = v;
#pragma unroll
        for (int o = 1; o < 32; o <<= 1) { int y = __shfl_up_sync(~0u, x, o); if (tid >= o) x += y; }
        bs[tid] = x - v;
    }
    __syncthreads();
    int i = blockIdx.x * 1024 + tid;
    if (i < n) { int r = g_tmp[i] + bs[blockIdx.x]; g_rowptr[i] = r; g_wptr[i] = r; }
    if (i == 0) g_rowptr[n] = total;
}
__global__ void k_gscan(int nb) {
    __shared__ int s[64];
    int tid = threadIdx.x;
    s[tid] = (tid < nb) ? g_gcnt[tid] : 0;
    __syncthreads();
    for (int o = 1; o < 64; o <<= 1) {
        int v = (tid >= o) ? s[tid - o] : 0;
        __syncthreads(); s[tid] += v; __syncthreads();
    }
    g_gptr[tid + 1] = s[tid];
    if (tid == 0) g_gptr[0] = 0;
}
__global__ void k_edge_scatter(const int* __restrict__ ei, int E, int n) {
    int i = blockIdx.x * blockDim.x + threadIdx.x;
    if (i >= E + n) return;
    int sv, dv;
    if (i < E) { sv = ei[i]; dv = ei[E + i]; } else { sv = dv = i - E; }
    g_col[atomicAdd(&g_wptr[dv], 1)] = sv;
}

// ---- tf32 mma GEMM (hi/lo in registers) + fused s/d epilogue ----
// Out[n,M] = A[n,K] @ W[K,M]; CTA 128x64, 8 warps (4m x 2n), warp tile 32x32.
// Fused: g_s/g_d[row*4 + blockIdx.y] = dot(Out_row[cb..cb+63], asrc/adst[cb..cb+63]).
__global__ __launch_bounds__(256) void k_gemm_mma(const float* __restrict__ A,
                                                 const float* __restrict__ W,
                                                 const float* __restrict__ asrc,
                                                 const float* __restrict__ adst,
                                                 float* __restrict__ Out,
                                                 int n, int K, int M) {
    __shared__ float As[128][36];  // [m][k]
    __shared__ float Bs[32][72];   // [k][n]
    __shared__ float sdbuf[2][128];
    int tid = threadIdx.x, lane = tid & 31, wid = tid >> 5;
    int warp_m = wid & 3, warp_n = wid >> 2;
    int rb = blockIdx.x * 128, cb = blockIdx.y * 64;
    int m0 = warp_m * 32, n0 = warp_n * 32;
    int row = lane >> 2, col = lane & 3;

    float acc[2][4][4];
#pragma unroll
    for (int a = 0; a < 2; a++)
#pragma unroll
        for (int b = 0; b < 4; b++)
#pragma unroll
            for (int q = 0; q < 4; q++) acc[a][b][q] = 0.f;

    for (int k0 = 0; k0 < K; k0 += 32) {
#pragma unroll
        for (int i = 0; i < 4; i++) {   // A tile 128x32
            int idx = tid + i * 256;
            int r = idx >> 3, c4 = (idx & 7) << 2;
            int gr = rb + r; if (gr >= n) gr = n - 1;
            *(float4*)&As[r][c4] = *(const float4*)(A + (size_t)gr * K + k0 + c4);
        }
#pragma unroll
        for (int i = 0; i < 2; i++) {   // B tile 32x64
            int idx = tid + i * 256;
            int kk = idx >> 4, c4 = (idx & 15) << 2;
            *(float4*)&Bs[kk][c4] = *(const float4*)(W + (size_t)(k0 + kk) * M + cb + c4);
        }
        __syncthreads();
#pragma unroll
        for (int kk = 0; kk < 32; kk += 8) {
            uint32_t ahi[2][4], alo[2][4], bhi[4][2], blo[4][2];
#pragma unroll
            for (int mt = 0; mt < 2; mt++)
#pragma unroll
                for (int q = 0; q < 4; q++) {
                    float v = As[m0 + mt * 16 + row + (q & 1) * 8][kk + col + (q >> 1) * 4];
                    float h = f2tf(v);
                    ahi[mt][q] = __float_as_uint(h);
                    alo[mt][q] = __float_as_uint(f2tf(v - h));
                }
#pragma unroll
            for (int nt = 0; nt < 4; nt++)
#pragma unroll
                for (int q = 0; q < 2; q++) {
                    float v = Bs[kk + col + q * 4][n0 + nt * 8 + row];
                    float h = f2tf(v);
                    bhi[nt][q] = __float_as_uint(h);
                    blo[nt][q] = __float_as_uint(f2tf(v - h));
                }
#pragma unroll
            for (int mt = 0; mt < 2; mt++)
#pragma unroll
                for (int nt = 0; nt < 4; nt++) {
                    mma8(acc[mt][nt], ahi[mt], bhi[nt]);
                    mma8(acc[mt][nt], ahi[mt], blo[nt]);
                    mma8(acc[mt][nt], alo[mt], bhi[nt]);
                }
        }
        __syncthreads();
    }

    // store Out + per-warp partial s/d over this warp's 32 columns
    float ws[2][2], wd[2][2];
#pragma unroll
    for (int mt = 0; mt < 2; mt++)
#pragma unroll
        for (int qh = 0; qh < 2; qh++) {
            int gr = rb + m0 + mt * 16 + row + qh * 8;
            float s = 0.f, d = 0.f;
#pragma unroll
            for (int nt = 0; nt < 4; nt++) {
                int cl = n0 + nt * 8 + col * 2;
                float v0 = acc[mt][nt][qh * 2], v1 = acc[mt][nt][qh * 2 + 1];
                if (gr < n)
                    *(float2*)(Out + (size_t)gr * M + cb + cl) = make_float2(v0, v1);
                s = fmaf(v0, __ldg(asrc + cb + cl), fmaf(v1, __ldg(asrc + cb + cl + 1), s));
                d = fmaf(v0, __ldg(adst + cb + cl), fmaf(v1, __ldg(adst + cb + cl + 1), d));
            }
            s += __shfl_xor_sync(~0u, s, 1); s += __shfl_xor_sync(~0u, s, 2);
            d += __shfl_xor_sync(~0u, d, 1); d += __shfl_xor_sync(~0u, d, 2);
            ws[mt][qh] = s; wd[mt][qh] = d;
        }
    // cross-warp (warp_n 0 + 1) reduction via smem; exact per-head dot
    if (warp_n == 1 && col == 0) {
#pragma unroll
        for (int mt = 0; mt < 2; mt++)
#pragma unroll
            for (int qh = 0; qh < 2; qh++) {
                int lr = m0 + mt * 16 + row + qh * 8;
                sdbuf[0][lr] = ws[mt][qh];
                sdbuf[1][lr] = wd[mt][qh];
            }
    }
    __syncthreads();
    if (warp_n == 0 && col == 0) {
#pragma unroll
        for (int mt = 0; mt < 2; mt++)
#pragma unroll
            for (int qh = 0; qh < 2; qh++) {
                int lr = m0 + mt * 16 + row + qh * 8;
                int gr = rb + lr;
                if (gr < n) {
                    g_s[gr * 4 + blockIdx.y] = ws[mt][qh] + sdbuf[0][lr];
                    g_d[gr * 4 + blockIdx.y] = wd[mt][qh] + sdbuf[1][lr];
                }
            }
    }
}

// ---- GAT attention + scatter + bias + ELU: warp per dst node ----
// SUM2: single head split across slots 0,1 (layer 3).
template <int H, int C, int SUM2>
__global__ void k_attn(const float* __restrict__ h, const float* __restrict__ bias,
                       float* __restrict__ out, int n) {
    int v = (blockIdx.x * blockDim.x + threadIdx.x) >> 5;
    int lane = threadIdx.x & 31;
    if (v >= n) return;
    int beg = g_rowptr[v], end = g_rowptr[v + 1];
    float dv[H], m[H];
#pragma unroll
    for (int t = 0; t < H; t++) {
        dv[t] = SUM2 ? (g_d[v * 4] + g_d[v * 4 + 1]) : g_d[v * 4 + t];
        m[t] = -1e30f;
    }
    for (int j = beg + lane; j < end; j += 32) {
        int u = g_col[j];
#pragma unroll
        for (int t = 0; t < H; t++) {
            float su = SUM2 ? (g_s[u * 4] + g_s[u * 4 + 1]) : g_s[u * 4 + t];
            float e = su + dv[t];
            e = (e > 0.f) ? e : 0.2f * e;
            m[t] = fmaxf(m[t], e);
        }
    }
#pragma unroll
    for (int t = 0; t < H; t++)
#pragma unroll
        for (int off = 16; off > 0; off >>= 1)
            m[t] = fmaxf(m[t], __shfl_xor_sync(~0u, m[t], off));

    constexpr int F = H * C / 32;
    int hh = (lane * F) / C;
    float mh = m[hh], dvh = dv[hh];
    float acc[F];
#pragma unroll
    for (int q = 0; q < F; q++) acc[q] = 0.f;
    float den = 0.f;
    for (int j = beg; j < end; j++) {
        int u = g_col[j];
        float su = SUM2 ? (g_s[u * 4] + g_s[u * 4 + 1]) : g_s[u * 4 + hh];
        float e = su + dvh;
        e = (e > 0.f) ? e : 0.2f * e;
        float ex = __expf(e - mh);
        den += ex;
        const float4* hp = (const float4*)(h + (size_t)u * (H * C)) + lane * (F / 4);
#pragma unroll
        for (int q = 0; q < F / 4; q++) {
            float4 hv = hp[q];
            acc[q * 4 + 0] = fmaf(ex, hv.x, acc[q * 4 + 0]);
            acc[q * 4 + 1] = fmaf(ex, hv.y, acc[q * 4 + 1]);
            acc[q * 4 + 2] = fmaf(ex, hv.z, acc[q * 4 + 2]);
            acc[q * 4 + 3] = fmaf(ex, hv.w, acc[q * 4 + 3]);
        }
    }
    float inv = 1.f / (den + 1e-16f);
#pragma unroll
    for (int q = 0; q < F; q++) {
        int c = lane * F + q;
        float o = acc[q] * inv + bias[c];
        o = (o > 0.f) ? o : expm1f(o);
        out[(size_t)v * (H * C) + c] = o;
    }
}

// ---- fused tail: Set2Set x3 + graph MLP + final MLP (block per graph) ----
__device__ __forceinline__ float dot128(const float* __restrict__ xp, const float* __restrict__ qv) {
    float e = 0.f;
#pragma unroll 8
    for (int k = 0; k < 32; k++) {
        float4 xv = ((const float4*)xp)[k];
        float4 q4 = *(const float4*)(qv + k * 4);
        e += xv.x * q4.x + xv.y * q4.y + xv.z * q4.z + xv.w * q4.w;
    }
    return e;
}
__global__ __launch_bounds__(128) void k_tail(
    const float* __restrict__ x,
    const float* __restrict__ Wih, const float* __restrict__ Whh,
    const float* __restrict__ bih, const float* __restrict__ bhh,
    const float* __restrict__ gfeat,
    const float* __restrict__ gW1, const float* __restrict__ gb1,
    const float* __restrict__ gW2, const float* __restrict__ gb2,
    const float* __restrict__ mW1, const float* __restrict__ mb1,
    const float* __restrict__ mW2, const float* __restrict__ mb2,
    float* __restrict__ out)
{
    int b = blockIdx.x, tid = threadIdx.x, lane = tid & 31, wid = tid >> 5;
    __shared__ float q[256], hv[128], cv[128], e_sh[2048], red[4], sval;
    __shared__ float gfh[64], gfo[32], hid[128];
    q[tid] = 0.f; q[tid + 128] = 0.f; hv[tid] = 0.f; cv[tid] = 0.f;
    int beg = g_gptr[b], cnt = g_gptr[b + 1] - beg;
    __syncthreads();

    for (int step = 0; step < 3; step++) {
        float a0 = bih[tid] + bhh[tid];
        float a1 = bih[128 + tid] + bhh[128 + tid];
        float a2 = bih[256 + tid] + bhh[256 + tid];
        float a3 = bih[384 + tid] + bhh[384 + tid];
        const float4* w0 = (const float4*)(Wih + (size_t)tid * 256);
        const float4* w1 = (const float4*)(Wih + (size_t)(128 + tid) * 256);
        const float4* w2 = (const float4*)(Wih + (size_t)(256 + tid) * 256);
        const float4* w3 = (const float4*)(Wih + (size_t)(384 + tid) * 256);
        for (int k = 0; k < 64; k++) {
            float4 qv = *(const float4*)&q[k * 4];
            float4 b0 = w0[k], b1v = w1[k], b2v = w2[k], b3v = w3[k];
            a0 += qv.x * b0.x + qv.y * b0.y + qv.z * b0.z + qv.w * b0.w;
            a1 += qv.x * b1v.x + qv.y * b1v.y + qv.z * b1v.z + qv.w * b1v.w;
            a2 += qv.x * b2v.x + qv.y * b2v.y + qv.z * b2v.z + qv.w * b2v.w;
            a3 += qv.x * b3v.x + qv.y * b3v.y + qv.z * b3v.z + qv.w * b3v.w;
        }
        const float4* u0 = (const float4*)(Whh + (size_t)tid * 128);
        const float4* u1 = (const float4*)(Whh + (size_t)(128 + tid) * 128);
        const float4* u2 = (const float4*)(Whh + (size_t)(256 + tid) * 128);
        const float4* u3 = (const float4*)(Whh + (size_t)(384 + tid) * 128);
        for (int k = 0; k < 32; k++) {
            float4 hvv = *(const float4*)&hv[k * 4];
            float4 b0 = u0[k], b1v = u1[k], b2v = u2[k], b3v = u3[k];
            a0 += hvv.x * b0.x + hvv.y * b0.y + hvv.z * b0.z + hvv.w * b0.w;
            a1 += hvv.x * b1v.x + hvv.y * b1v.y + hvv.z * b1v.z + hvv.w * b1v.w;
            a2 += hvv.x * b2v.x + hvv.y * b2v.y + hvv.z * b2v.z + hvv.w * b2v.w;
            a3 += hvv.x * b3v.x + hvv.y * b3v.y + hvv.z * b3v.z + hvv.w * b3v.w;
        }
        float ig = 1.f / (1.f + __expf(-a0));
        float fg = 1.f / (1.f + __expf(-a1));
        float gg = tanhf(a2);
        float og = 1.f / (1.f + __expf(-a3));
        float cc = fg * cv[tid] + ig * gg;
        float hh = og * tanhf(cc);
        __syncthreads();
        cv[tid] = cc; hv[tid] = hh;
        __syncthreads();

        float lmax = -1e30f;
        for (int i = tid; i < cnt; i += 128) {
            float e = dot128(x + (size_t)(beg + i) * 128, hv);
            if (i < 2048) e_sh[i] = e;
            lmax = fmaxf(lmax, e);
        }
#pragma unroll
        for (int o = 16; o; o >>= 1) lmax = fmaxf(lmax, __shfl_xor_sync(~0u, lmax, o));
        if (lane == 0) red[wid] = lmax;
        __syncthreads();
        if (tid == 0) sval = fmaxf(fmaxf(red[0], red[1]), fmaxf(red[2], red[3]));
        __syncthreads();
        float emax = sval;
        __syncthreads();
        float lsum = 0.f;
        for (int i = tid; i < cnt; i += 128) {
            float e = (i < 2048) ? e_sh[i] : dot128(x + (size_t)(beg + i) * 128, hv);
            float a = __expf(e - emax);
            if (i < 2048) e_sh[i] = a;
            lsum += a;
        }
#pragma unroll
        for (int o = 16; o; o >>= 1) lsum += __shfl_xor_sync(~0u, lsum, o);
        if (lane == 0) red[wid] = lsum;
        __syncthreads();
        if (tid == 0) sval = red[0] + red[1] + red[2] + red[3];
        __syncthreads();
        float inv = 1.f / (sval + 1e-16f);
        float r = 0.f;
        for (int i = 0; i < cnt; i++) {
            float a = (i < 2048) ? e_sh[i]
                                 : __expf(dot128(x + (size_t)(beg + i) * 128, hv) - emax);
            r = fmaf(a, x[(size_t)(beg + i) * 128 + tid], r);
        }
        __syncthreads();
        q[tid] = hv[tid];
        q[128 + tid] = r * inv;
        __syncthreads();
    }

    if (tid < 64) {
        float a = gb1[tid];
        for (int k = 0; k < 9; k++) a = fmaf(gfeat[b * 9 + k], gW1[k * 64 + tid], a);
        gfh[tid] = fmaxf(a, 0.f);
    }
    __syncthreads();
    if (tid < 32) {
        float o = gb2[tid];
        for (int k = 0; k < 64; k++) o = fmaf(gfh[k], gW2[k * 32 + tid], o);
        gfo[tid] = o;
    }
    __syncthreads();
    float a = mb1[tid];
    for (int k = 0; k < 256; k++) a = fmaf(q[k], mW1[k * 128 + tid], a);
    for (int k = 0; k < 32; k++) a = fmaf(gfo[k], mW1[(256 + k) * 128 + tid], a);
    hid[tid] = fmaxf(a, 0.f);
    __syncthreads();
    if (tid < 4) {
        float o = mb2[tid];
        for (int k = 0; k < 128; k++) o = fmaf(hid[k], mW2[k * 4 + tid], o);
        out[b * 4 + tid] = o;
    }
}

// ---- launch ----
extern "C" void kernel_launch(void* const* d_in, const int* in_sizes, int n_in,
                              void* d_out, int out_size) {
    const float* x      = (const float*)d_in[0];
    const int*   ei     = (const int*)d_in[1];
    const int*   batch  = (const int*)d_in[2];
    const float* gfeat  = (const float*)d_in[3];
    const float* W1     = (const float*)d_in[4];
    const float* a_src1 = (const float*)d_in[5];
    const float* a_dst1 = (const float*)d_in[6];
    const float* b1     = (const float*)d_in[7];
    const float* W2     = (const float*)d_in[8];
    const float* a_src2 = (const float*)d_in[9];
    const float* a_dst2 = (const float*)d_in[10];
    const float* b2     = (const float*)d_in[11];
    const float* W3     = (const float*)d_in[12];
    const float* a_src3 = (const float*)d_in[13];
    const float* a_dst3 = (const float*)d_in[14];
    const float* b3     = (const float*)d_in[15];
    const float* Wih    = (const float*)d_in[16];
    const float* Whh    = (const float*)d_in[17];
    const float* bih    = (const float*)d_in[18];
    const float* bhh    = (const float*)d_in[19];
    const float* gW1    = (const float*)d_in[20];
    const float* gb1    = (const float*)d_in[21];
    const float* gW2    = (const float*)d_in[22];
    const float* gb2    = (const float*)d_in[23];
    const float* mW1    = (const float*)d_in[24];
    const float* mb1    = (const float*)d_in[25];
    const float* mW2    = (const float*)d_in[26];
    const float* mb2    = (const float*)d_in[27];

    int n  = in_sizes[0] / 128;
    int E  = in_sizes[1] / 2;
    int nb = in_sizes[3] / 9;
    int TE = E + n;

    float *ph, *pfeat;
    cudaGetSymbolAddress((void**)&ph, g_h);
    cudaGetSymbolAddress((void**)&pfeat, g_feat);

    int gx = (n + 127) / 128;
    int attn_blocks = (n * 32 + 255) / 256;

    k_init<<<(n + 255) / 256, 256>>>(n);
    k_hist<<<(TE + 255) / 256, 256>>>(ei, batch, E, n);
    k_scan_part<<<(n + 1023) / 1024, 1024>>>(n);
    // layer-1 GEMM early (independent of CSR); also puts the heavy kernel in the ncu slot
    k_gemm_mma<<<dim3(gx, 4), 256>>>(x, W1, a_src1, a_dst1, ph, n, 128, 256);
    k_scan_apply<<<(n + 1023) / 1024, 1024>>>(n, TE);
    k_edge_scatter<<<(TE + 255) / 256, 256>>>(ei, E, n);

    k_attn<4, 64, 0><<<attn_blocks, 256>>>(ph, b1, pfeat, n);
    k_gemm_mma<<<dim3(gx, 4), 256>>>(pfeat, W2, a_src2, a_dst2, ph, n, 256, 256);
    k_attn<4, 64, 0><<<attn_blocks, 256>>>(ph, b2, pfeat, n);
    k_gemm_mma<<<dim3(gx, 2), 256>>>(pfeat, W3, a_src3, a_dst3, ph, n, 256, 128);
    k_attn<1, 128, 1><<<attn_blocks, 256>>>(ph, b3, pfeat, n);

    k_gscan<<<1, 64>>>(nb);
    k_tail<<<nb, 128>>>(pfeat, Wih, Whh, bih, bhh, gfeat,
                        gW1, gb1, gW2, gb2, mW1, mb1, mW2, mb2, (float*)d_out);
}

// round 7
// speedup vs baseline: 2.4436x; 1.0035x over previous
#include <cuda_runtime.h>
#include <math.h>
#include <stdint.h>

#define NMAX 20000
#define EMAX 320000
#define TEMAX (EMAX + NMAX)
#define BMAXG 64

__device__ __align__(16) float g_h[NMAX * 256];
__device__ __align__(16) float g_feat[NMAX * 256];
__device__ float g_s[NMAX * 4];
__device__ float g_d[NMAX * 4];
__device__ int g_rowptr[NMAX + 1];
__device__ int g_wptr[NMAX];
__device__ int g_col[TEMAX];
__device__ int g_gcnt[BMAXG];
__device__ int g_gptr[BMAXG + 1];
__device__ int g_tmp[NMAX];
__device__ int g_blksum[32];

__device__ __forceinline__ float f2tf(float a) {
    uint32_t r;
    asm("cvt.rn.tf32.f32 %0, %1;" : "=r"(r) : "f"(a));
    return __uint_as_float(r);
}
__device__ __forceinline__ void mma8(float* c, const uint32_t* a, const uint32_t* b) {
    asm volatile(
        "mma.sync.aligned.m16n8k8.row.col.f32.tf32.tf32.f32 "
        "{%0,%1,%2,%3}, {%4,%5,%6,%7}, {%8,%9}, {%0,%1,%2,%3};"
        : "+f"(c[0]), "+f"(c[1]), "+f"(c[2]), "+f"(c[3])
        : "r"(a[0]), "r"(a[1]), "r"(a[2]), "r"(a[3]), "r"(b[0]), "r"(b[1]));
}

// ---- init + CSR ----
__global__ void k_init(int n) {
    int i = blockIdx.x * blockDim.x + threadIdx.x;
    if (i < n) g_wptr[i] = 0;
    if (i < BMAXG) g_gcnt[i] = 0;
}
__global__ void k_hist(const int* __restrict__ ei, const int* __restrict__ batch, int E, int n) {
    int i = blockIdx.x * blockDim.x + threadIdx.x;
    if (i < E + n) {
        int dv = (i < E) ? ei[E + i] : (i - E);
        atomicAdd(&g_wptr[dv], 1);
    }
    if (i < n) atomicAdd(&g_gcnt[batch[i]], 1);
}
__global__ __launch_bounds__(1024) void k_scan_part(int n) {
    __shared__ int wsum[32];
    int tid = threadIdx.x, lane = tid & 31, wid = tid >> 5;
    int i = blockIdx.x * 1024 + tid;
    int v = (i < n) ? g_wptr[i] : 0;
    int x = v;
#pragma unroll
    for (int o = 1; o < 32; o <<= 1) { int y = __shfl_up_sync(~0u, x, o); if (lane >= o) x += y; }
    if (lane == 31) wsum[wid] = x;
    __syncthreads();
    if (wid == 0) {
        int w = wsum[lane];
#pragma unroll
        for (int o = 1; o < 32; o <<= 1) { int y = __shfl_up_sync(~0u, w, o); if (lane >= o) w += y; }
        wsum[lane] = w;
    }
    __syncthreads();
    int excl = x - v + ((wid > 0) ? wsum[wid - 1] : 0);
    if (i < n) g_tmp[i] = excl;
    if (tid == 1023) g_blksum[blockIdx.x] = wsum[31];
}
__global__ __launch_bounds__(1024) void k_scan_apply(int n, int total) {
    __shared__ int bs[32];
    int tid = threadIdx.x;
    if (tid < 32) {
        int nblk = gridDim.x;
        int v = (tid < nblk) ? g_blksum[tid] : 0;
        int x = v;
#pragma unroll
        for (int o = 1; o < 32; o <<= 1) { int y = __shfl_up_sync(~0u, x, o); if (tid >= o) x += y; }
        bs[tid] = x - v;
    }
    __syncthreads();
    int i = blockIdx.x * 1024 + tid;
    if (i < n) { int r = g_tmp[i] + bs[blockIdx.x]; g_rowptr[i] = r; g_wptr[i] = r; }
    if (i == 0) g_rowptr[n] = total;
}
__global__ void k_gscan(int nb) {
    __shared__ int s[64];
    int tid = threadIdx.x;
    s[tid] = (tid < nb) ? g_gcnt[tid] : 0;
    __syncthreads();
    for (int o = 1; o < 64; o <<= 1) {
        int v = (tid >= o) ? s[tid - o] : 0;
        __syncthreads(); s[tid] += v; __syncthreads();
    }
    g_gptr[tid + 1] = s[tid];
    if (tid == 0) g_gptr[0] = 0;
}
__global__ void k_edge_scatter(const int* __restrict__ ei, int E, int n) {
    int i = blockIdx.x * blockDim.x + threadIdx.x;
    if (i >= E + n) return;
    int sv, dv;
    if (i < E) { sv = ei[i]; dv = ei[E + i]; } else { sv = dv = i - E; }
    g_col[atomicAdd(&g_wptr[dv], 1)] = sv;
}

// ---- tf32 mma GEMM (A hi/lo in smem, B hi/lo in regs) + fused s/d epilogue ----
__global__ __launch_bounds__(256) void k_gemm_mma(const float* __restrict__ A,
                                                 const float* __restrict__ W,
                                                 const float* __restrict__ asrc,
                                                 const float* __restrict__ adst,
                                                 float* __restrict__ Out,
                                                 int n, int K, int M) {
    __shared__ float Ah[128][36], Al[128][36];  // 36KB
    __shared__ float Bs[32][72];                 // 9.2KB
    __shared__ float sdbuf[2][128];              // 1KB  (total 46.2KB < 48KB)
    int tid = threadIdx.x, lane = tid & 31, wid = tid >> 5;
    int warp_m = wid & 3, warp_n = wid >> 2;
    int rb = blockIdx.x * 128, cb = blockIdx.y * 64;
    int m0 = warp_m * 32, n0 = warp_n * 32;
    int row = lane >> 2, col = lane & 3;

    float acc[2][4][4];
#pragma unroll
    for (int a = 0; a < 2; a++)
#pragma unroll
        for (int b = 0; b < 4; b++)
#pragma unroll
            for (int q = 0; q < 4; q++) acc[a][b][q] = 0.f;

    for (int k0 = 0; k0 < K; k0 += 32) {
#pragma unroll
        for (int i = 0; i < 4; i++) {   // A tile 128x32 -> hi/lo at store
            int idx = tid + i * 256;
            int r = idx >> 3, c4 = (idx & 7) << 2;
            int gr = rb + r; if (gr >= n) gr = n - 1;
            float4 v = *(const float4*)(A + (size_t)gr * K + k0 + c4);
            float4 h, l;
            h.x = f2tf(v.x); l.x = f2tf(v.x - h.x);
            h.y = f2tf(v.y); l.y = f2tf(v.y - h.y);
            h.z = f2tf(v.z); l.z = f2tf(v.z - h.z);
            h.w = f2tf(v.w); l.w = f2tf(v.w - h.w);
            *(float4*)&Ah[r][c4] = h;
            *(float4*)&Al[r][c4] = l;
        }
#pragma unroll
        for (int i = 0; i < 2; i++) {   // B tile 32x64 fp32
            int idx = tid + i * 256;
            int kk = idx >> 4, c4 = (idx & 15) << 2;
            *(float4*)&Bs[kk][c4] = *(const float4*)(W + (size_t)(k0 + kk) * M + cb + c4);
        }
        __syncthreads();
#pragma unroll
        for (int kk = 0; kk < 32; kk += 8) {
            uint32_t ahi[2][4], alo[2][4], bhi[4][2], blo[4][2];
#pragma unroll
            for (int mt = 0; mt < 2; mt++)
#pragma unroll
                for (int q = 0; q < 4; q++) {
                    int r = m0 + mt * 16 + row + (q & 1) * 8, c = kk + col + (q >> 1) * 4;
                    ahi[mt][q] = __float_as_uint(Ah[r][c]);
                    alo[mt][q] = __float_as_uint(Al[r][c]);
                }
#pragma unroll
            for (int nt = 0; nt < 4; nt++)
#pragma unroll
                for (int q = 0; q < 2; q++) {
                    float v = Bs[kk + col + q * 4][n0 + nt * 8 + row];
                    float h = f2tf(v);
                    bhi[nt][q] = __float_as_uint(h);
                    blo[nt][q] = __float_as_uint(f2tf(v - h));
                }
#pragma unroll
            for (int mt = 0; mt < 2; mt++)
#pragma unroll
                for (int nt = 0; nt < 4; nt++) {
                    mma8(acc[mt][nt], ahi[mt], bhi[nt]);
                    mma8(acc[mt][nt], ahi[mt], blo[nt]);
                    mma8(acc[mt][nt], alo[mt], bhi[nt]);
                }
        }
        __syncthreads();
    }

    float ws[2][2], wd[2][2];
#pragma unroll
    for (int mt = 0; mt < 2; mt++)
#pragma unroll
        for (int qh = 0; qh < 2; qh++) {
            int gr = rb + m0 + mt * 16 + row + qh * 8;
            float s = 0.f, d = 0.f;
#pragma unroll
            for (int nt = 0; nt < 4; nt++) {
                int cl = n0 + nt * 8 + col * 2;
                float v0 = acc[mt][nt][qh * 2], v1 = acc[mt][nt][qh * 2 + 1];
                if (gr < n)
                    *(float2*)(Out + (size_t)gr * M + cb + cl) = make_float2(v0, v1);
                s = fmaf(v0, __ldg(asrc + cb + cl), fmaf(v1, __ldg(asrc + cb + cl + 1), s));
                d = fmaf(v0, __ldg(adst + cb + cl), fmaf(v1, __ldg(adst + cb + cl + 1), d));
            }
            s += __shfl_xor_sync(~0u, s, 1); s += __shfl_xor_sync(~0u, s, 2);
            d += __shfl_xor_sync(~0u, d, 1); d += __shfl_xor_sync(~0u, d, 2);
            ws[mt][qh] = s; wd[mt][qh] = d;
        }
    if (warp_n == 1 && col == 0) {
#pragma unroll
        for (int mt = 0; mt < 2; mt++)
#pragma unroll
            for (int qh = 0; qh < 2; qh++) {
                int lr = m0 + mt * 16 + row + qh * 8;
                sdbuf[0][lr] = ws[mt][qh];
                sdbuf[1][lr] = wd[mt][qh];
            }
    }
    __syncthreads();
    if (warp_n == 0 && col == 0) {
#pragma unroll
        for (int mt = 0; mt < 2; mt++)
#pragma unroll
            for (int qh = 0; qh < 2; qh++) {
                int lr = m0 + mt * 16 + row + qh * 8;
                int gr = rb + lr;
                if (gr < n) {
                    g_s[gr * 4 + blockIdx.y] = ws[mt][qh] + sdbuf[0][lr];
                    g_d[gr * 4 + blockIdx.y] = wd[mt][qh] + sdbuf[1][lr];
                }
            }
    }
}

// ---- GAT attention (no-max softmax, 4-edge unrolled) + bias + ELU ----
template <int H, int C, int SUM2>
__global__ void k_attn(const float* __restrict__ h, const float* __restrict__ bias,
                       float* __restrict__ out, int n) {
    int v = (blockIdx.x * blockDim.x + threadIdx.x) >> 5;
    int lane = threadIdx.x & 31;
    if (v >= n) return;
    int beg = g_rowptr[v], end = g_rowptr[v + 1];
    constexpr int F = H * C / 32;   // floats per lane (8 or 4)
    constexpr int FV = F / 4;       // float4s per lane (2 or 1)
    int hh = (lane * F) / C;
    float dvh = SUM2 ? (g_d[v * 4] + g_d[v * 4 + 1]) : g_d[v * 4 + hh];
    float acc[F];
#pragma unroll
    for (int q = 0; q < F; q++) acc[q] = 0.f;
    float den = 0.f;

    int j = beg;
    for (; j + 4 <= end; j += 4) {
        int u0 = g_col[j], u1 = g_col[j + 1], u2 = g_col[j + 2], u3 = g_col[j + 3];
        float s0 = SUM2 ? (g_s[u0 * 4] + g_s[u0 * 4 + 1]) : g_s[u0 * 4 + hh];
        float s1 = SUM2 ? (g_s[u1 * 4] + g_s[u1 * 4 + 1]) : g_s[u1 * 4 + hh];
        float s2 = SUM2 ? (g_s[u2 * 4] + g_s[u2 * 4 + 1]) : g_s[u2 * 4 + hh];
        float s3 = SUM2 ? (g_s[u3 * 4] + g_s[u3 * 4 + 1]) : g_s[u3 * 4 + hh];
        const float4* p0 = (const float4*)(h + (size_t)u0 * (H * C)) + lane * FV;
        const float4* p1 = (const float4*)(h + (size_t)u1 * (H * C)) + lane * FV;
        const float4* p2 = (const float4*)(h + (size_t)u2 * (H * C)) + lane * FV;
        const float4* p3 = (const float4*)(h + (size_t)u3 * (H * C)) + lane * FV;
        float4 r0[FV], r1[FV], r2[FV], r3[FV];
#pragma unroll
        for (int q = 0; q < FV; q++) { r0[q] = p0[q]; r1[q] = p1[q]; r2[q] = p2[q]; r3[q] = p3[q]; }
        float e0 = s0 + dvh; e0 = (e0 > 0.f) ? e0 : 0.2f * e0; float x0 = __expf(e0);
        float e1 = s1 + dvh; e1 = (e1 > 0.f) ? e1 : 0.2f * e1; float x1 = __expf(e1);
        float e2 = s2 + dvh; e2 = (e2 > 0.f) ? e2 : 0.2f * e2; float x2 = __expf(e2);
        float e3 = s3 + dvh; e3 = (e3 > 0.f) ? e3 : 0.2f * e3; float x3 = __expf(e3);
        den += (x0 + x1) + (x2 + x3);
#pragma unroll
        for (int q = 0; q < FV; q++) {
            acc[q * 4 + 0] = fmaf(x0, r0[q].x, fmaf(x1, r1[q].x, fmaf(x2, r2[q].x, fmaf(x3, r3[q].x, acc[q * 4 + 0]))));
            acc[q * 4 + 1] = fmaf(x0, r0[q].y, fmaf(x1, r1[q].y, fmaf(x2, r2[q].y, fmaf(x3, r3[q].y, acc[q * 4 + 1]))));
            acc[q * 4 + 2] = fmaf(x0, r0[q].z, fmaf(x1, r1[q].z, fmaf(x2, r2[q].z, fmaf(x3, r3[q].z, acc[q * 4 + 2]))));
            acc[q * 4 + 3] = fmaf(x0, r0[q].w, fmaf(x1, r1[q].w, fmaf(x2, r2[q].w, fmaf(x3, r3[q].w, acc[q * 4 + 3]))));
        }
    }
    for (; j < end; j++) {
        int u = g_col[j];
        float su = SUM2 ? (g_s[u * 4] + g_s[u * 4 + 1]) : g_s[u * 4 + hh];
        float e = su + dvh;
        e = (e > 0.f) ? e : 0.2f * e;
        float ex = __expf(e);
        den += ex;
        const float4* hp = (const float4*)(h + (size_t)u * (H * C)) + lane * FV;
#pragma unroll
        for (int q = 0; q < FV; q++) {
            float4 hv = hp[q];
            acc[q * 4 + 0] = fmaf(ex, hv.x, acc[q * 4 + 0]);
            acc[q * 4 + 1] = fmaf(ex, hv.y, acc[q * 4 + 1]);
            acc[q * 4 + 2] = fmaf(ex, hv.z, acc[q * 4 + 2]);
            acc[q * 4 + 3] = fmaf(ex, hv.w, acc[q * 4 + 3]);
        }
    }
    float inv = 1.f / (den + 1e-16f);
#pragma unroll
    for (int q = 0; q < F; q++) {
        int c = lane * F + q;
        float o = acc[q] * inv + bias[c];
        o = (o > 0.f) ? o : expm1f(o);
        out[(size_t)v * (H * C) + c] = o;
    }
}

// ---- fused tail: Set2Set x3 + graph MLP + final MLP (block per graph) ----
__device__ __forceinline__ float dot128(const float* __restrict__ xp, const float* __restrict__ qv) {
    float e = 0.f;
#pragma unroll 8
    for (int k = 0; k < 32; k++) {
        float4 xv = ((const float4*)xp)[k];
        float4 q4 = *(const float4*)(qv + k * 4);
        e += xv.x * q4.x + xv.y * q4.y + xv.z * q4.z + xv.w * q4.w;
    }
    return e;
}
__global__ __launch_bounds__(128) void k_tail(
    const float* __restrict__ x,
    const float* __restrict__ Wih, const float* __restrict__ Whh,
    const float* __restrict__ bih, const float* __restrict__ bhh,
    const float* __restrict__ gfeat,
    const float* __restrict__ gW1, const float* __restrict__ gb1,
    const float* __restrict__ gW2, const float* __restrict__ gb2,
    const float* __restrict__ mW1, const float* __restrict__ mb1,
    const float* __restrict__ mW2, const float* __restrict__ mb2,
    float* __restrict__ out)
{
    int b = blockIdx.x, tid = threadIdx.x, lane = tid & 31, wid = tid >> 5;
    __shared__ float q[256], hv[128], cv[128], e_sh[2048], red[4], sval;
    __shared__ float gfh[64], gfo[32], hid[128];
    q[tid] = 0.f; q[tid + 128] = 0.f; hv[tid] = 0.f; cv[tid] = 0.f;
    int beg = g_gptr[b], cnt = g_gptr[b + 1] - beg;
    __syncthreads();

    for (int step = 0; step < 3; step++) {
        float a0 = bih[tid] + bhh[tid];
        float a1 = bih[128 + tid] + bhh[128 + tid];
        float a2 = bih[256 + tid] + bhh[256 + tid];
        float a3 = bih[384 + tid] + bhh[384 + tid];
        const float4* w0 = (const float4*)(Wih + (size_t)tid * 256);
        const float4* w1 = (const float4*)(Wih + (size_t)(128 + tid) * 256);
        const float4* w2 = (const float4*)(Wih + (size_t)(256 + tid) * 256);
        const float4* w3 = (const float4*)(Wih + (size_t)(384 + tid) * 256);
        for (int k = 0; k < 64; k++) {
            float4 qv = *(const float4*)&q[k * 4];
            float4 b0 = w0[k], b1v = w1[k], b2v = w2[k], b3v = w3[k];
            a0 += qv.x * b0.x + qv.y * b0.y + qv.z * b0.z + qv.w * b0.w;
            a1 += qv.x * b1v.x + qv.y * b1v.y + qv.z * b1v.z + qv.w * b1v.w;
            a2 += qv.x * b2v.x + qv.y * b2v.y + qv.z * b2v.z + qv.w * b2v.w;
            a3 += qv.x * b3v.x + qv.y * b3v.y + qv.z * b3v.z + qv.w * b3v.w;
        }
        const float4* u0 = (const float4*)(Whh + (size_t)tid * 128);
        const float4* u1 = (const float4*)(Whh + (size_t)(128 + tid) * 128);
        const float4* u2 = (const float4*)(Whh + (size_t)(256 + tid) * 128);
        const float4* u3 = (const float4*)(Whh + (size_t)(384 + tid) * 128);
        for (int k = 0; k < 32; k++) {
            float4 hvv = *(const float4*)&hv[k * 4];
            float4 b0 = u0[k], b1v = u1[k], b2v = u2[k], b3v = u3[k];
            a0 += hvv.x * b0.x + hvv.y * b0.y + hvv.z * b0.z + hvv.w * b0.w;
            a1 += hvv.x * b1v.x + hvv.y * b1v.y + hvv.z * b1v.z + hvv.w * b1v.w;
            a2 += hvv.x * b2v.x + hvv.y * b2v.y + hvv.z * b2v.z + hvv.w * b2v.w;
            a3 += hvv.x * b3v.x + hvv.y * b3v.y + hvv.z * b3v.z + hvv.w * b3v.w;
        }
        float ig = 1.f / (1.f + __expf(-a0));
        float fg = 1.f / (1.f + __expf(-a1));
        float gg = tanhf(a2);
        float og = 1.f / (1.f + __expf(-a3));
        float cc = fg * cv[tid] + ig * gg;
        float hh = og * tanhf(cc);
        __syncthreads();
        cv[tid] = cc; hv[tid] = hh;
        __syncthreads();

        float lmax = -1e30f;
        for (int i = tid; i < cnt; i += 128) {
            float e = dot128(x + (size_t)(beg + i) * 128, hv);
            if (i < 2048) e_sh[i] = e;
            lmax = fmaxf(lmax, e);
        }
#pragma unroll
        for (int o = 16; o; o >>= 1) lmax = fmaxf(lmax, __shfl_xor_sync(~0u, lmax, o));
        if (lane == 0) red[wid] = lmax;
        __syncthreads();
        if (tid == 0) sval = fmaxf(fmaxf(red[0], red[1]), fmaxf(red[2], red[3]));
        __syncthreads();
        float emax = sval;
        __syncthreads();
        float lsum = 0.f;
        for (int i = tid; i < cnt; i += 128) {
            float e = (i < 2048) ? e_sh[i] : dot128(x + (size_t)(beg + i) * 128, hv);
            float a = __expf(e - emax);
            if (i < 2048) e_sh[i] = a;
            lsum += a;
        }
#pragma unroll
        for (int o = 16; o; o >>= 1) lsum += __shfl_xor_sync(~0u, lsum, o);
        if (lane == 0) red[wid] = lsum;
        __syncthreads();
        if (tid == 0) sval = red[0] + red[1] + red[2] + red[3];
        __syncthreads();
        float inv = 1.f / (sval + 1e-16f);
        float r = 0.f;
        for (int i = 0; i < cnt; i++) {
            float a = (i < 2048) ? e_sh[i]
                                 : __expf(dot128(x + (size_t)(beg + i) * 128, hv) - emax);
            r = fmaf(a, x[(size_t)(beg + i) * 128 + tid], r);
        }
        __syncthreads();
        q[tid] = hv[tid];
        q[128 + tid] = r * inv;
        __syncthreads();
    }

    if (tid < 64) {
        float a = gb1[tid];
        for (int k = 0; k < 9; k++) a = fmaf(gfeat[b * 9 + k], gW1[k * 64 + tid], a);
        gfh[tid] = fmaxf(a, 0.f);
    }
    __syncthreads();
    if (tid < 32) {
        float o = gb2[tid];
        for (int k = 0; k < 64; k++) o = fmaf(gfh[k], gW2[k * 32 + tid], o);
        gfo[tid] = o;
    }
    __syncthreads();
    float a = mb1[tid];
    for (int k = 0; k < 256; k++) a = fmaf(q[k], mW1[k * 128 + tid], a);
    for (int k = 0; k < 32; k++) a = fmaf(gfo[k], mW1[(256 + k) * 128 + tid], a);
    hid[tid] = fmaxf(a, 0.f);
    __syncthreads();
    if (tid < 4) {
        float o = mb2[tid];
        for (int k = 0; k < 128; k++) o = fmaf(hid[k], mW2[k * 4 + tid], o);
        out[b * 4 + tid] = o;
    }
}

// ---- launch ----
extern "C" void kernel_launch(void* const* d_in, const int* in_sizes, int n_in,
                              void* d_out, int out_size) {
    const float* x      = (const float*)d_in[0];
    const int*   ei     = (const int*)d_in[1];
    const int*   batch  = (const int*)d_in[2];
    const float* gfeat  = (const float*)d_in[3];
    const float* W1     = (const float*)d_in[4];
    const float* a_src1 = (const float*)d_in[5];
    const float* a_dst1 = (const float*)d_in[6];
    const float* b1     = (const float*)d_in[7];
    const float* W2     = (const float*)d_in[8];
    const float* a_src2 = (const float*)d_in[9];
    const float* a_dst2 = (const float*)d_in[10];
    const float* b2     = (const float*)d_in[11];
    const float* W3     = (const float*)d_in[12];
    const float* a_src3 = (const float*)d_in[13];
    const float* a_dst3 = (const float*)d_in[14];
    const float* b3     = (const float*)d_in[15];
    const float* Wih    = (const float*)d_in[16];
    const float* Whh    = (const float*)d_in[17];
    const float* bih    = (const float*)d_in[18];
    const float* bhh    = (const float*)d_in[19];
    const float* gW1    = (const float*)d_in[20];
    const float* gb1    = (const float*)d_in[21];
    const float* gW2    = (const float*)d_in[22];
    const float* gb2    = (const float*)d_in[23];
    const float* mW1    = (const float*)d_in[24];
    const float* mb1    = (const float*)d_in[25];
    const float* mW2    = (const float*)d_in[26];
    const float* mb2    = (const float*)d_in[27];

    int n  = in_sizes[0] / 128;
    int E  = in_sizes[1] / 2;
    int nb = in_sizes[3] / 9;
    int TE = E + n;

    float *ph, *pfeat;
    cudaGetSymbolAddress((void**)&ph, g_h);
    cudaGetSymbolAddress((void**)&pfeat, g_feat);

    int gx = (n + 127) / 128;
    int attn_blocks = (n * 32 + 255) / 256;

    k_init<<<(n + 255) / 256, 256>>>(n);
    k_hist<<<(TE + 255) / 256, 256>>>(ei, batch, E, n);
    k_scan_part<<<(n + 1023) / 1024, 1024>>>(n);
    k_gemm_mma<<<dim3(gx, 4), 256>>>(x, W1, a_src1, a_dst1, ph, n, 128, 256);
    k_scan_apply<<<(n + 1023) / 1024, 1024>>>(n, TE);
    k_edge_scatter<<<(TE + 255) / 256, 256>>>(ei, E, n);

    k_attn<4, 64, 0><<<attn_blocks, 256>>>(ph, b1, pfeat, n);
    k_gemm_mma<<<dim3(gx, 4), 256>>>(pfeat, W2, a_src2, a_dst2, ph, n, 256, 256);
    k_attn<4, 64, 0><<<attn_blocks, 256>>>(ph, b2, pfeat, n);
    k_gemm_mma<<<dim3(gx, 2), 256>>>(pfeat, W3, a_src3, a_dst3, ph, n, 256, 128);
    k_attn<1, 128, 1><<<attn_blocks, 256>>>(ph, b3, pfeat, n);

    k_gscan<<<1, 64>>>(nb);
    k_tail<<<nb, 128>>>(pfeat, Wih, Whh, bih, bhh, gfeat,
                        gW1, gb1, gW2, gb2, mW1, mb1, mW2, mb2, (float*)d_out);
}

// round 9
// speedup vs baseline: 2.5978x; 1.0631x over previous
#include <cuda_runtime.h>
#include <math.h>
#include <stdint.h>

#define NMAX 20000
#define EMAX 320000
#define TEMAX (EMAX + NMAX)
#define BMAXG 64

__device__ __align__(16) float g_h[NMAX * 256];
__device__ __align__(16) float g_feat[NMAX * 256];
__device__ float g_s[NMAX * 4];
__device__ float g_d[NMAX * 4];
__device__ int g_rowptr[NMAX + 1];
__device__ int g_wptr[NMAX];
__device__ int g_col[TEMAX];
__device__ int g_gcnt[BMAXG];
__device__ int g_gptr[BMAXG + 1];
__device__ int g_tmp[NMAX];
__device__ int g_blksum[32];

__device__ __forceinline__ float f2tf(float a) {
    uint32_t r;
    asm("cvt.rn.tf32.f32 %0, %1;" : "=r"(r) : "f"(a));
    return __uint_as_float(r);
}
__device__ __forceinline__ void mma8(float* c, const uint32_t* a, const uint32_t* b) {
    asm volatile(
        "mma.sync.aligned.m16n8k8.row.col.f32.tf32.tf32.f32 "
        "{%0,%1,%2,%3}, {%4,%5,%6,%7}, {%8,%9}, {%0,%1,%2,%3};"
        : "+f"(c[0]), "+f"(c[1]), "+f"(c[2]), "+f"(c[3])
        : "r"(a[0]), "r"(a[1]), "r"(a[2]), "r"(a[3]), "r"(b[0]), "r"(b[1]));
}

// ---- init + CSR ----
__global__ void k_init(int n) {
    int i = blockIdx.x * blockDim.x + threadIdx.x;
    if (i < n) g_wptr[i] = 0;
    if (i < BMAXG) g_gcnt[i] = 0;
}
__global__ void k_hist(const int* __restrict__ ei, const int* __restrict__ batch, int E, int n) {
    int i = blockIdx.x * blockDim.x + threadIdx.x;
    if (i < E + n) {
        int dv = (i < E) ? ei[E + i] : (i - E);
        atomicAdd(&g_wptr[dv], 1);
    }
    if (i < n) atomicAdd(&g_gcnt[batch[i]], 1);
}
__global__ __launch_bounds__(1024) void k_scan_part(int n) {
    __shared__ int wsum[32];
    int tid = threadIdx.x, lane = tid & 31, wid = tid >> 5;
    int i = blockIdx.x * 1024 + tid;
    int v = (i < n) ? g_wptr[i] : 0;
    int x = v;
#pragma unroll
    for (int o = 1; o < 32; o <<= 1) { int y = __shfl_up_sync(~0u, x, o); if (lane >= o) x += y; }
    if (lane == 31) wsum[wid] = x;
    __syncthreads();
    if (wid == 0) {
        int w = wsum[lane];
#pragma unroll
        for (int o = 1; o < 32; o <<= 1) { int y = __shfl_up_sync(~0u, w, o); if (lane >= o) w += y; }
        wsum[lane] = w;
    }
    __syncthreads();
    int excl = x - v + ((wid > 0) ? wsum[wid - 1] : 0);
    if (i < n) g_tmp[i] = excl;
    if (tid == 1023) g_blksum[blockIdx.x] = wsum[31];
}
__global__ __launch_bounds__(1024) void k_scan_apply(int n, int total) {
    __shared__ int bs[32];
    int tid = threadIdx.x;
    if (tid < 32) {
        int nblk = gridDim.x;
        int v = (tid < nblk) ? g_blksum[tid] : 0;
        int x = v;
#pragma unroll
        for (int o = 1; o < 32; o <<= 1) { int y = __shfl_up_sync(~0u, x, o); if (tid >= o) x += y; }
        bs[tid] = x - v;
    }
    __syncthreads();
    int i = blockIdx.x * 1024 + tid;
    if (i < n) { int r = g_tmp[i] + bs[blockIdx.x]; g_rowptr[i] = r; g_wptr[i] = r; }
    if (i == 0) g_rowptr[n] = total;
}
__global__ void k_gscan(int nb) {
    __shared__ int s[64];
    int tid = threadIdx.x;
    s[tid] = (tid < nb) ? g_gcnt[tid] : 0;
    __syncthreads();
    for (int o = 1; o < 64; o <<= 1) {
        int v = (tid >= o) ? s[tid - o] : 0;
        __syncthreads(); s[tid] += v; __syncthreads();
    }
    g_gptr[tid + 1] = s[tid];
    if (tid == 0) g_gptr[0] = 0;
}
__global__ void k_edge_scatter(const int* __restrict__ ei, int E, int n) {
    int i = blockIdx.x * blockDim.x + threadIdx.x;
    if (i >= E + n) return;
    int sv, dv;
    if (i < E) { sv = ei[i]; dv = ei[E + i]; } else { sv = dv = i - E; }
    g_col[atomicAdd(&g_wptr[dv], 1)] = sv;
}

// ---- tf32 mma GEMM (A hi/lo in smem, B hi/lo in regs) + fused s/d epilogue ----
__global__ __launch_bounds__(256) void k_gemm_mma(const float* __restrict__ A,
                                                 const float* __restrict__ W,
                                                 const float* __restrict__ asrc,
                                                 const float* __restrict__ adst,
                                                 float* __restrict__ Out,
                                                 int n, int K, int M) {
    __shared__ float Ah[128][36], Al[128][36];
    __shared__ float Bs[32][72];
    __shared__ float sdbuf[2][128];
    int tid = threadIdx.x, lane = tid & 31, wid = tid >> 5;
    int warp_m = wid & 3, warp_n = wid >> 2;
    int rb = blockIdx.x * 128, cb = blockIdx.y * 64;
    int m0 = warp_m * 32, n0 = warp_n * 32;
    int row = lane >> 2, col = lane & 3;

    float acc[2][4][4];
#pragma unroll
    for (int a = 0; a < 2; a++)
#pragma unroll
        for (int b = 0; b < 4; b++)
#pragma unroll
            for (int q = 0; q < 4; q++) acc[a][b][q] = 0.f;

    for (int k0 = 0; k0 < K; k0 += 32) {
#pragma unroll
        for (int i = 0; i < 4; i++) {
            int idx = tid + i * 256;
            int r = idx >> 3, c4 = (idx & 7) << 2;
            int gr = rb + r; if (gr >= n) gr = n - 1;
            float4 v = *(const float4*)(A + (size_t)gr * K + k0 + c4);
            float4 h, l;
            h.x = f2tf(v.x); l.x = f2tf(v.x - h.x);
            h.y = f2tf(v.y); l.y = f2tf(v.y - h.y);
            h.z = f2tf(v.z); l.z = f2tf(v.z - h.z);
            h.w = f2tf(v.w); l.w = f2tf(v.w - h.w);
            *(float4*)&Ah[r][c4] = h;
            *(float4*)&Al[r][c4] = l;
        }
#pragma unroll
        for (int i = 0; i < 2; i++) {
            int idx = tid + i * 256;
            int kk = idx >> 4, c4 = (idx & 15) << 2;
            *(float4*)&Bs[kk][c4] = *(const float4*)(W + (size_t)(k0 + kk) * M + cb + c4);
        }
        __syncthreads();
#pragma unroll
        for (int kk = 0; kk < 32; kk += 8) {
            uint32_t ahi[2][4], alo[2][4], bhi[4][2], blo[4][2];
#pragma unroll
            for (int mt = 0; mt < 2; mt++)
#pragma unroll
                for (int q = 0; q < 4; q++) {
                    int r = m0 + mt * 16 + row + (q & 1) * 8, c = kk + col + (q >> 1) * 4;
                    ahi[mt][q] = __float_as_uint(Ah[r][c]);
                    alo[mt][q] = __float_as_uint(Al[r][c]);
                }
#pragma unroll
            for (int nt = 0; nt < 4; nt++)
#pragma unroll
                for (int q = 0; q < 2; q++) {
                    float v = Bs[kk + col + q * 4][n0 + nt * 8 + row];
                    float h = f2tf(v);
                    bhi[nt][q] = __float_as_uint(h);
                    blo[nt][q] = __float_as_uint(f2tf(v - h));
                }
#pragma unroll
            for (int mt = 0; mt < 2; mt++)
#pragma unroll
                for (int nt = 0; nt < 4; nt++) {
                    mma8(acc[mt][nt], ahi[mt], bhi[nt]);
                    mma8(acc[mt][nt], ahi[mt], blo[nt]);
                    mma8(acc[mt][nt], alo[mt], bhi[nt]);
                }
        }
        __syncthreads();
    }

    float ws[2][2], wd[2][2];
#pragma unroll
    for (int mt = 0; mt < 2; mt++)
#pragma unroll
        for (int qh = 0; qh < 2; qh++) {
            int gr = rb + m0 + mt * 16 + row + qh * 8;
            float s = 0.f, d = 0.f;
#pragma unroll
            for (int nt = 0; nt < 4; nt++) {
                int cl = n0 + nt * 8 + col * 2;
                float v0 = acc[mt][nt][qh * 2], v1 = acc[mt][nt][qh * 2 + 1];
                if (gr < n)
                    *(float2*)(Out + (size_t)gr * M + cb + cl) = make_float2(v0, v1);
                s = fmaf(v0, __ldg(asrc + cb + cl), fmaf(v1, __ldg(asrc + cb + cl + 1), s));
                d = fmaf(v0, __ldg(adst + cb + cl), fmaf(v1, __ldg(adst + cb + cl + 1), d));
            }
            s += __shfl_xor_sync(~0u, s, 1); s += __shfl_xor_sync(~0u, s, 2);
            d += __shfl_xor_sync(~0u, d, 1); d += __shfl_xor_sync(~0u, d, 2);
            ws[mt][qh] = s; wd[mt][qh] = d;
        }
    if (warp_n == 1 && col == 0) {
#pragma unroll
        for (int mt = 0; mt < 2; mt++)
#pragma unroll
            for (int qh = 0; qh < 2; qh++) {
                int lr = m0 + mt * 16 + row + qh * 8;
                sdbuf[0][lr] = ws[mt][qh];
                sdbuf[1][lr] = wd[mt][qh];
            }
    }
    __syncthreads();
    if (warp_n == 0 && col == 0) {
#pragma unroll
        for (int mt = 0; mt < 2; mt++)
#pragma unroll
            for (int qh = 0; qh < 2; qh++) {
                int lr = m0 + mt * 16 + row + qh * 8;
                int gr = rb + lr;
                if (gr < n) {
                    g_s[gr * 4 + blockIdx.y] = ws[mt][qh] + sdbuf[0][lr];
                    g_d[gr * 4 + blockIdx.y] = wd[mt][qh] + sdbuf[1][lr];
                }
            }
    }
}

// ---- GAT attention, 2 warps per dst node (layers 1/2: H=4, C=64, row = 256 floats) ----
__global__ void k_attn2(const float* __restrict__ h, const float* __restrict__ bias,
                        float* __restrict__ out, int n) {
    int gw = (blockIdx.x * blockDim.x + threadIdx.x) >> 5;
    int lane = threadIdx.x & 31;
    int v = gw >> 1, half = gw & 1;
    if (v >= n) return;
    int c4 = half * 32 + lane;       // float4 index within the 64-float4 row
    int hh = c4 >> 4;                // head
    float dvh = g_d[v * 4 + hh];
    int beg = g_rowptr[v], end = g_rowptr[v + 1];
    float ax = 0.f, ay = 0.f, az = 0.f, aw = 0.f;
    float den = 0.f;

    int j = beg;
    for (; j + 4 <= end; j += 4) {
        int u0 = g_col[j], u1 = g_col[j + 1], u2 = g_col[j + 2], u3 = g_col[j + 3];
        float s0 = g_s[u0 * 4 + hh], s1 = g_s[u1 * 4 + hh];
        float s2 = g_s[u2 * 4 + hh], s3 = g_s[u3 * 4 + hh];
        float4 r0 = ((const float4*)(h + (size_t)u0 * 256))[c4];
        float4 r1 = ((const float4*)(h + (size_t)u1 * 256))[c4];
        float4 r2 = ((const float4*)(h + (size_t)u2 * 256))[c4];
        float4 r3 = ((const float4*)(h + (size_t)u3 * 256))[c4];
        float e0 = s0 + dvh; e0 = (e0 > 0.f) ? e0 : 0.2f * e0; float x0 = __expf(e0);
        float e1 = s1 + dvh; e1 = (e1 > 0.f) ? e1 : 0.2f * e1; float x1 = __expf(e1);
        float e2 = s2 + dvh; e2 = (e2 > 0.f) ? e2 : 0.2f * e2; float x2 = __expf(e2);
        float e3 = s3 + dvh; e3 = (e3 > 0.f) ? e3 : 0.2f * e3; float x3 = __expf(e3);
        den += (x0 + x1) + (x2 + x3);
        ax = fmaf(x0, r0.x, fmaf(x1, r1.x, fmaf(x2, r2.x, fmaf(x3, r3.x, ax))));
        ay = fmaf(x0, r0.y, fmaf(x1, r1.y, fmaf(x2, r2.y, fmaf(x3, r3.y, ay))));
        az = fmaf(x0, r0.z, fmaf(x1, r1.z, fmaf(x2, r2.z, fmaf(x3, r3.z, az))));
        aw = fmaf(x0, r0.w, fmaf(x1, r1.w, fmaf(x2, r2.w, fmaf(x3, r3.w, aw))));
    }
    for (; j < end; j++) {
        int u = g_col[j];
        float e = g_s[u * 4 + hh] + dvh;
        e = (e > 0.f) ? e : 0.2f * e;
        float ex = __expf(e);
        den += ex;
        float4 r = ((const float4*)(h + (size_t)u * 256))[c4];
        ax = fmaf(ex, r.x, ax); ay = fmaf(ex, r.y, ay);
        az = fmaf(ex, r.z, az); aw = fmaf(ex, r.w, aw);
    }
    float inv = 1.f / (den + 1e-16f);
    int c0 = c4 * 4;
    float4 bv = *(const float4*)(bias + c0);
    float o0 = ax * inv + bv.x; o0 = (o0 > 0.f) ? o0 : expm1f(o0);
    float o1 = ay * inv + bv.y; o1 = (o1 > 0.f) ? o1 : expm1f(o1);
    float o2 = az * inv + bv.z; o2 = (o2 > 0.f) ? o2 : expm1f(o2);
    float o3 = aw * inv + bv.w; o3 = (o3 > 0.f) ? o3 : expm1f(o3);
    *(float4*)(out + (size_t)v * 256 + c0) = make_float4(o0, o1, o2, o3);
}

// ---- layer-3 attention: 1 warp per node, H=1 C=128 (row = 128 floats!) ----
__global__ void k_attn3(const float* __restrict__ h, const float* __restrict__ bias,
                        float* __restrict__ out, int n) {
    int v = (blockIdx.x * blockDim.x + threadIdx.x) >> 5;
    int lane = threadIdx.x & 31;
    if (v >= n) return;
    float dvh = g_d[v * 4] + g_d[v * 4 + 1];
    int beg = g_rowptr[v], end = g_rowptr[v + 1];
    float ax = 0.f, ay = 0.f, az = 0.f, aw = 0.f;
    float den = 0.f;
    int j = beg;
    for (; j + 4 <= end; j += 4) {
        int u0 = g_col[j], u1 = g_col[j + 1], u2 = g_col[j + 2], u3 = g_col[j + 3];
        float s0 = g_s[u0 * 4] + g_s[u0 * 4 + 1];
        float s1 = g_s[u1 * 4] + g_s[u1 * 4 + 1];
        float s2 = g_s[u2 * 4] + g_s[u2 * 4 + 1];
        float s3 = g_s[u3 * 4] + g_s[u3 * 4 + 1];
        float4 r0 = ((const float4*)(h + (size_t)u0 * 128))[lane];
        float4 r1 = ((const float4*)(h + (size_t)u1 * 128))[lane];
        float4 r2 = ((const float4*)(h + (size_t)u2 * 128))[lane];
        float4 r3 = ((const float4*)(h + (size_t)u3 * 128))[lane];
        float e0 = s0 + dvh; e0 = (e0 > 0.f) ? e0 : 0.2f * e0; float x0 = __expf(e0);
        float e1 = s1 + dvh; e1 = (e1 > 0.f) ? e1 : 0.2f * e1; float x1 = __expf(e1);
        float e2 = s2 + dvh; e2 = (e2 > 0.f) ? e2 : 0.2f * e2; float x2 = __expf(e2);
        float e3 = s3 + dvh; e3 = (e3 > 0.f) ? e3 : 0.2f * e3; float x3 = __expf(e3);
        den += (x0 + x1) + (x2 + x3);
        ax = fmaf(x0, r0.x, fmaf(x1, r1.x, fmaf(x2, r2.x, fmaf(x3, r3.x, ax))));
        ay = fmaf(x0, r0.y, fmaf(x1, r1.y, fmaf(x2, r2.y, fmaf(x3, r3.y, ay))));
        az = fmaf(x0, r0.z, fmaf(x1, r1.z, fmaf(x2, r2.z, fmaf(x3, r3.z, az))));
        aw = fmaf(x0, r0.w, fmaf(x1, r1.w, fmaf(x2, r2.w, fmaf(x3, r3.w, aw))));
    }
    for (; j < end; j++) {
        int u = g_col[j];
        float e = g_s[u * 4] + g_s[u * 4 + 1] + dvh;
        e = (e > 0.f) ? e : 0.2f * e;
        float ex = __expf(e);
        den += ex;
        float4 r = ((const float4*)(h + (size_t)u * 128))[lane];
        ax = fmaf(ex, r.x, ax); ay = fmaf(ex, r.y, ay);
        az = fmaf(ex, r.z, az); aw = fmaf(ex, r.w, aw);
    }
    float inv = 1.f / (den + 1e-16f);
    int c0 = lane * 4;
    float4 bv = *(const float4*)(bias + c0);
    float o0 = ax * inv + bv.x; o0 = (o0 > 0.f) ? o0 : expm1f(o0);
    float o1 = ay * inv + bv.y; o1 = (o1 > 0.f) ? o1 : expm1f(o1);
    float o2 = az * inv + bv.z; o2 = (o2 > 0.f) ? o2 : expm1f(o2);
    float o3 = aw * inv + bv.w; o3 = (o3 > 0.f) ? o3 : expm1f(o3);
    *(float4*)(out + (size_t)v * 128 + c0) = make_float4(o0, o1, o2, o3);
}

// ---- fused tail: Set2Set x3 + graph MLP + final MLP (block per graph) ----
__device__ __forceinline__ float dot128(const float* __restrict__ xp, const float* __restrict__ qv) {
    float e = 0.f;
#pragma unroll 8
    for (int k = 0; k < 32; k++) {
        float4 xv = ((const float4*)xp)[k];
        float4 q4 = *(const float4*)(qv + k * 4);
        e += xv.x * q4.x + xv.y * q4.y + xv.z * q4.z + xv.w * q4.w;
    }
    return e;
}
__global__ __launch_bounds__(128) void k_tail(
    const float* __restrict__ x,
    const float* __restrict__ Wih, const float* __restrict__ Whh,
    const float* __restrict__ bih, const float* __restrict__ bhh,
    const float* __restrict__ gfeat,
    const float* __restrict__ gW1, const float* __restrict__ gb1,
    const float* __restrict__ gW2, const float* __restrict__ gb2,
    const float* __restrict__ mW1, const float* __restrict__ mb1,
    const float* __restrict__ mW2, const float* __restrict__ mb2,
    float* __restrict__ out)
{
    int b = blockIdx.x, tid = threadIdx.x, lane = tid & 31, wid = tid >> 5;
    __shared__ float q[256], hv[128], cv[128], e_sh[2048], red[4], sval;
    __shared__ float gfh[64], gfo[32], hid[128];
    q[tid] = 0.f; q[tid + 128] = 0.f; hv[tid] = 0.f; cv[tid] = 0.f;
    int beg = g_gptr[b], cnt = g_gptr[b + 1] - beg;
    __syncthreads();

    for (int step = 0; step < 3; step++) {
        float a0 = bih[tid] + bhh[tid];
        float a1 = bih[128 + tid] + bhh[128 + tid];
        float a2 = bih[256 + tid] + bhh[256 + tid];
        float a3 = bih[384 + tid] + bhh[384 + tid];
        const float4* w0 = (const float4*)(Wih + (size_t)tid * 256);
        const float4* w1 = (const float4*)(Wih + (size_t)(128 + tid) * 256);
        const float4* w2 = (const float4*)(Wih + (size_t)(256 + tid) * 256);
        const float4* w3 = (const float4*)(Wih + (size_t)(384 + tid) * 256);
        for (int k = 0; k < 64; k++) {
            float4 qv = *(const float4*)&q[k * 4];
            float4 b0 = w0[k], b1v = w1[k], b2v = w2[k], b3v = w3[k];
            a0 += qv.x * b0.x + qv.y * b0.y + qv.z * b0.z + qv.w * b0.w;
            a1 += qv.x * b1v.x + qv.y * b1v.y + qv.z * b1v.z + qv.w * b1v.w;
            a2 += qv.x * b2v.x + qv.y * b2v.y + qv.z * b2v.z + qv.w * b2v.w;
            a3 += qv.x * b3v.x + qv.y * b3v.y + qv.z * b3v.z + qv.w * b3v.w;
        }
        const float4* u0 = (const float4*)(Whh + (size_t)tid * 128);
        const float4* u1 = (const float4*)(Whh + (size_t)(128 + tid) * 128);
        const float4* u2 = (const float4*)(Whh + (size_t)(256 + tid) * 128);
        const float4* u3 = (const float4*)(Whh + (size_t)(384 + tid) * 128);
        for (int k = 0; k < 32; k++) {
            float4 hvv = *(const float4*)&hv[k * 4];
            float4 b0 = u0[k], b1v = u1[k], b2v = u2[k], b3v = u3[k];
            a0 += hvv.x * b0.x + hvv.y * b0.y + hvv.z * b0.z + hvv.w * b0.w;
            a1 += hvv.x * b1v.x + hvv.y * b1v.y + hvv.z * b1v.z + hvv.w * b1v.w;
            a2 += hvv.x * b2v.x + hvv.y * b2v.y + hvv.z * b2v.z + hvv.w * b2v.w;
            a3 += hvv.x * b3v.x + hvv.y * b3v.y + hvv.z * b3v.z + hvv.w * b3v.w;
        }
        float ig = 1.f / (1.f + __expf(-a0));
        float fg = 1.f / (1.f + __expf(-a1));
        float gg = tanhf(a2);
        float og = 1.f / (1.f + __expf(-a3));
        float cc = fg * cv[tid] + ig * gg;
        float hh = og * tanhf(cc);
        __syncthreads();
        cv[tid] = cc; hv[tid] = hh;
        __syncthreads();

        float lmax = -1e30f;
        for (int i = tid; i < cnt; i += 128) {
            float e = dot128(x + (size_t)(beg + i) * 128, hv);
            if (i < 2048) e_sh[i] = e;
            lmax = fmaxf(lmax, e);
        }
#pragma unroll
        for (int o = 16; o; o >>= 1) lmax = fmaxf(lmax, __shfl_xor_sync(~0u, lmax, o));
        if (lane == 0) red[wid] = lmax;
        __syncthreads();
        if (tid == 0) sval = fmaxf(fmaxf(red[0], red[1]), fmaxf(red[2], red[3]));
        __syncthreads();
        float emax = sval;
        __syncthreads();
        float lsum = 0.f;
        for (int i = tid; i < cnt; i += 128) {
            float e = (i < 2048) ? e_sh[i] : dot128(x + (size_t)(beg + i) * 128, hv);
            float a = __expf(e - emax);
            if (i < 2048) e_sh[i] = a;
            lsum += a;
        }
#pragma unroll
        for (int o = 16; o; o >>= 1) lsum += __shfl_xor_sync(~0u, lsum, o);
        if (lane == 0) red[wid] = lsum;
        __syncthreads();
        if (tid == 0) sval = red[0] + red[1] + red[2] + red[3];
        __syncthreads();
        float inv = 1.f / (sval + 1e-16f);
        float r = 0.f;
        for (int i = 0; i < cnt; i++) {
            float a = (i < 2048) ? e_sh[i]
                                 : __expf(dot128(x + (size_t)(beg + i) * 128, hv) - emax);
            r = fmaf(a, x[(size_t)(beg + i) * 128 + tid], r);
        }
        __syncthreads();
        q[tid] = hv[tid];
        q[128 + tid] = r * inv;
        __syncthreads();
    }

    if (tid < 64) {
        float a = gb1[tid];
        for (int k = 0; k < 9; k++) a = fmaf(gfeat[b * 9 + k], gW1[k * 64 + tid], a);
        gfh[tid] = fmaxf(a, 0.f);
    }
    __syncthreads();
    if (tid < 32) {
        float o = gb2[tid];
        for (int k = 0; k < 64; k++) o = fmaf(gfh[k], gW2[k * 32 + tid], o);
        gfo[tid] = o;
    }
    __syncthreads();
    float a = mb1[tid];
    for (int k = 0; k < 256; k++) a = fmaf(q[k], mW1[k * 128 + tid], a);
    for (int k = 0; k < 32; k++) a = fmaf(gfo[k], mW1[(256 + k) * 128 + tid], a);
    hid[tid] = fmaxf(a, 0.f);
    __syncthreads();
    if (tid < 4) {
        float o = mb2[tid];
        for (int k = 0; k < 128; k++) o = fmaf(hid[k], mW2[k * 4 + tid], o);
        out[b * 4 + tid] = o;
    }
}

// ---- launch ----
extern "C" void kernel_launch(void* const* d_in, const int* in_sizes, int n_in,
                              void* d_out, int out_size) {
    const float* x      = (const float*)d_in[0];
    const int*   ei     = (const int*)d_in[1];
    const int*   batch  = (const int*)d_in[2];
    const float* gfeat  = (const float*)d_in[3];
    const float* W1     = (const float*)d_in[4];
    const float* a_src1 = (const float*)d_in[5];
    const float* a_dst1 = (const float*)d_in[6];
    const float* b1     = (const float*)d_in[7];
    const float* W2     = (const float*)d_in[8];
    const float* a_src2 = (const float*)d_in[9];
    const float* a_dst2 = (const float*)d_in[10];
    const float* b2     = (const float*)d_in[11];
    const float* W3     = (const float*)d_in[12];
    const float* a_src3 = (const float*)d_in[13];
    const float* a_dst3 = (const float*)d_in[14];
    const float* b3     = (const float*)d_in[15];
    const float* Wih    = (const float*)d_in[16];
    const float* Whh    = (const float*)d_in[17];
    const float* bih    = (const float*)d_in[18];
    const float* bhh    = (const float*)d_in[19];
    const float* gW1    = (const float*)d_in[20];
    const float* gb1    = (const float*)d_in[21];
    const float* gW2    = (const float*)d_in[22];
    const float* gb2    = (const float*)d_in[23];
    const float* mW1    = (const float*)d_in[24];
    const float* mb1    = (const float*)d_in[25];
    const float* mW2    = (const float*)d_in[26];
    const float* mb2    = (const float*)d_in[27];

    int n  = in_sizes[0] / 128;
    int E  = in_sizes[1] / 2;
    int nb = in_sizes[3] / 9;
    int TE = E + n;

    float *ph, *pfeat;
    cudaGetSymbolAddress((void**)&ph, g_h);
    cudaGetSymbolAddress((void**)&pfeat, g_feat);

    int gx = (n + 127) / 128;
    int attn2_blocks = (n * 64 + 255) / 256;   // 2 warps per node
    int attn3_blocks = (n * 32 + 255) / 256;

    k_init<<<(n + 255) / 256, 256>>>(n);
    k_hist<<<(TE + 255) / 256, 256>>>(ei, batch, E, n);
    k_scan_part<<<(n + 1023) / 1024, 1024>>>(n);
    k_gemm_mma<<<dim3(gx, 4), 256>>>(x, W1, a_src1, a_dst1, ph, n, 128, 256);
    k_scan_apply<<<(n + 1023) / 1024, 1024>>>(n, TE);
    k_edge_scatter<<<(TE + 255) / 256, 256>>>(ei, E, n);

    k_attn2<<<attn2_blocks, 256>>>(ph, b1, pfeat, n);
    k_gemm_mma<<<dim3(gx, 4), 256>>>(pfeat, W2, a_src2, a_dst2, ph, n, 256, 256);
    k_attn2<<<attn2_blocks, 256>>>(ph, b2, pfeat, n);
    k_gemm_mma<<<dim3(gx, 2), 256>>>(pfeat, W3, a_src3, a_dst3, ph, n, 256, 128);
    k_attn3<<<attn3_blocks, 256>>>(ph, b3, pfeat, n);

    k_gscan<<<1, 64>>>(nb);
    k_tail<<<nb, 128>>>(pfeat, Wih, Whh, bih, bhh, gfeat,
                        gW1, gb1, gW2, gb2, mW1, mb1, mW2, mb2, (float*)d_out);
}